// round 1
// baseline (speedup 1.0000x reference)
#include <cuda_runtime.h>
#include <math.h>

// Problem constants (fixed by dataset): N=50000, E=1600000, D=256, De=128, H=128
#define Hh 128
#define TE 64
#define THREADS 256
#define NMAX 50000

__device__ float g_ws[NMAX];
__device__ float g_wd[NMAX];
__device__ float g_sum;

__device__ __forceinline__ float lrelu(float v) { return v > 0.f ? v : 0.01f * v; }

__global__ void zero_kernel() { g_sum = 0.f; }

// -------------------- Node MLPs (src & dst) --------------------
// X: [N, 256]. Computes g_ws[n] = mlp_src(X[n]), g_wd[n] = mlp_dst(X[n]).
__global__ void __launch_bounds__(THREADS, 2)
node_kernel(const float* __restrict__ X, int N,
            const float* __restrict__ Ws1, const float* __restrict__ bs1,
            const float* __restrict__ ws2, const float* __restrict__ bs2,
            const float* __restrict__ Wd1, const float* __restrict__ bd1,
            const float* __restrict__ wd2, const float* __restrict__ bd2)
{
    extern __shared__ float sm[];
    float* sX  = sm;                 // [TE][256]
    float* sW  = sm + TE * 256;      // [32][128] staged W1 chunk
    float* sB1 = sW + 32 * Hh;       // [128]
    float* sW2 = sB1 + Hh;           // [128]

    const int tid = threadIdx.x;
    const int hg = tid & 31;         // h group: h = 4*hg .. 4*hg+3
    const int eg = tid >> 5;         // node group: nodes 8*eg .. 8*eg+7
    const int lane = tid & 31;

    const int numTiles = (N + TE - 1) / TE;
    for (int tile = blockIdx.x; tile < numTiles; tile += gridDim.x) {
        const int n0 = tile * TE;
        __syncthreads();
        // load X tile (row-major, coalesced float4)
        for (int idx = tid; idx < TE * 64; idx += THREADS) {
            int e = idx >> 6;        // 64 float4 per 256-col row
            int c = idx & 63;
            float4 v = make_float4(0.f, 0.f, 0.f, 0.f);
            if (n0 + e < N) v = ((const float4*)(X + (size_t)(n0 + e) * 256))[c];
            ((float4*)(sX + e * 256))[c] = v;
        }
        __syncthreads();

        for (int pass = 0; pass < 2; ++pass) {
            const float* W1 = pass ? Wd1 : Ws1;
            const float* b1 = pass ? bd1 : bs1;
            const float* w2 = pass ? wd2 : ws2;
            const float  b2v = pass ? wd2[0] * 0.f + bd2[0] : bs2[0];
            float* outp = pass ? g_wd : g_ws;

            __syncthreads();
            if (tid < Hh) { sB1[tid] = b1[tid]; sW2[tid] = w2[tid]; }
            __syncthreads();

            float acc[8][4];
            {
                float4 bv = ((const float4*)sB1)[hg];
                #pragma unroll
                for (int i = 0; i < 8; i++) {
                    acc[i][0] = bv.x; acc[i][1] = bv.y; acc[i][2] = bv.z; acc[i][3] = bv.w;
                }
            }

            for (int k0 = 0; k0 < 256; k0 += 32) {
                __syncthreads();
                for (int idx = tid; idx < 32 * 32; idx += THREADS) {
                    int r = idx >> 5;
                    int c = idx & 31;
                    ((float4*)(sW + r * Hh))[c] = ((const float4*)(W1 + (size_t)(k0 + r) * Hh))[c];
                }
                __syncthreads();
                #pragma unroll
                for (int k4 = 0; k4 < 8; ++k4) {
                    float4 xr[8];
                    #pragma unroll
                    for (int i = 0; i < 8; i++)
                        xr[i] = ((const float4*)(sX + (8 * eg + i) * 256))[(k0 >> 2) + k4];
                    #pragma unroll
                    for (int kk = 0; kk < 4; ++kk) {
                        float4 w = ((const float4*)(sW + (4 * k4 + kk) * Hh))[hg];
                        #pragma unroll
                        for (int i = 0; i < 8; i++) {
                            float x = (&xr[i].x)[kk];
                            acc[i][0] += x * w.x; acc[i][1] += x * w.y;
                            acc[i][2] += x * w.z; acc[i][3] += x * w.w;
                        }
                    }
                }
            }

            float4 w2v = ((const float4*)sW2)[hg];
            float myOut = 0.f;
            #pragma unroll
            for (int i = 0; i < 8; i++) {
                float p = lrelu(acc[i][0]) * w2v.x + lrelu(acc[i][1]) * w2v.y +
                          lrelu(acc[i][2]) * w2v.z + lrelu(acc[i][3]) * w2v.w;
                p += __shfl_xor_sync(0xFFFFFFFFu, p, 16);
                p += __shfl_xor_sync(0xFFFFFFFFu, p, 8);
                p += __shfl_xor_sync(0xFFFFFFFFu, p, 4);
                p += __shfl_xor_sync(0xFFFFFFFFu, p, 2);
                p += __shfl_xor_sync(0xFFFFFFFFu, p, 1);
                if (lane == i) myOut = p + b2v;
            }
            if (lane < 8) {
                int n = n0 + 8 * eg + lane;
                if (n < N) outp[n] = myOut;
            }
        }
    }
}

// -------------------- Edge MLP + gather + sigmoid + reduction --------------------
__global__ void __launch_bounds__(THREADS, 2)
edge_kernel(const float* __restrict__ X, int E,
            const float* __restrict__ W1, const float* __restrict__ b1,
            const float* __restrict__ w2, const float* __restrict__ b2,
            const float* __restrict__ noise, const int* __restrict__ src,
            const int* __restrict__ dst, float* __restrict__ aug)
{
    extern __shared__ float sm[];
    float* sW  = sm;                   // [128][128] full W1
    float* sX  = sm + 128 * 128;       // [TE][128]
    float* sB1 = sX + TE * 128;        // [128]
    float* sW2 = sB1 + Hh;             // [128]
    __shared__ float sPart[8];

    const int tid = threadIdx.x;
    const int hg = tid & 31;
    const int eg = tid >> 5;
    const int lane = tid & 31;

    for (int idx = tid; idx < 128 * 32; idx += THREADS)
        ((float4*)sW)[idx] = ((const float4*)W1)[idx];
    if (tid < Hh) { sB1[tid] = b1[tid]; sW2[tid] = w2[tid]; }
    const float b2v = b2[0];
    __syncthreads();

    float localSum = 0.f;
    const int numTiles = (E + TE - 1) / TE;
    for (int tile = blockIdx.x; tile < numTiles; tile += gridDim.x) {
        const int e0 = tile * TE;
        __syncthreads();
        for (int idx = tid; idx < TE * 32; idx += THREADS) {
            int e = idx >> 5;          // 32 float4 per 128-col row
            int c = idx & 31;
            float4 v = make_float4(0.f, 0.f, 0.f, 0.f);
            if (e0 + e < E) v = ((const float4*)(X + (size_t)(e0 + e) * 128))[c];
            ((float4*)(sX + e * 128))[c] = v;
        }
        __syncthreads();

        float acc[8][4];
        {
            float4 bv = ((const float4*)sB1)[hg];
            #pragma unroll
            for (int i = 0; i < 8; i++) {
                acc[i][0] = bv.x; acc[i][1] = bv.y; acc[i][2] = bv.z; acc[i][3] = bv.w;
            }
        }

        #pragma unroll 4
        for (int k4 = 0; k4 < 32; ++k4) {
            float4 xr[8];
            #pragma unroll
            for (int i = 0; i < 8; i++)
                xr[i] = ((const float4*)(sX + (8 * eg + i) * 128))[k4];
            #pragma unroll
            for (int kk = 0; kk < 4; ++kk) {
                float4 w = ((const float4*)(sW + (4 * k4 + kk) * 128))[hg];
                #pragma unroll
                for (int i = 0; i < 8; i++) {
                    float x = (&xr[i].x)[kk];
                    acc[i][0] += x * w.x; acc[i][1] += x * w.y;
                    acc[i][2] += x * w.z; acc[i][3] += x * w.w;
                }
            }
        }

        float4 w2v = ((const float4*)sW2)[hg];
        float myWe = 0.f;
        #pragma unroll
        for (int i = 0; i < 8; i++) {
            float p = lrelu(acc[i][0]) * w2v.x + lrelu(acc[i][1]) * w2v.y +
                      lrelu(acc[i][2]) * w2v.z + lrelu(acc[i][3]) * w2v.w;
            p += __shfl_xor_sync(0xFFFFFFFFu, p, 16);
            p += __shfl_xor_sync(0xFFFFFFFFu, p, 8);
            p += __shfl_xor_sync(0xFFFFFFFFu, p, 4);
            p += __shfl_xor_sync(0xFFFFFFFFu, p, 2);
            p += __shfl_xor_sync(0xFFFFFFFFu, p, 1);
            if (lane == i) myWe = p + b2v;
        }
        if (lane < 8) {
            int e = e0 + 8 * eg + lane;
            if (e < E) {
                float weight = myWe + __ldg(&g_ws[src[e]]) + __ldg(&g_wd[dst[e]]);
                float u = noise[e];
                float eps = (2.f * 1e-4f - 1.f) * u + (1.f - 1e-4f);
                float gate = (logf(eps) - log1pf(-eps) + weight) * 2.0f; // /TEMP, TEMP=0.5
                float a = 1.f / (1.f + expf(-gate));
                aug[e] = a;
                localSum += a;
            }
        }
    }

    // deterministic-enough block reduction, one atomic per block
    #pragma unroll
    for (int o = 16; o > 0; o >>= 1) localSum += __shfl_xor_sync(0xFFFFFFFFu, localSum, o);
    if (lane == 0) sPart[eg] = localSum;
    __syncthreads();
    if (tid == 0) {
        float s = 0.f;
        #pragma unroll
        for (int i = 0; i < 8; i++) s += sPart[i];
        atomicAdd(&g_sum, s);
    }
}

__global__ void finalize_kernel(float* out0, float invE) {
    *out0 = 1.f - g_sum * invE;
}

// -------------------- host --------------------
extern "C" void kernel_launch(void* const* d_in, const int* in_sizes, int n_in,
                              void* d_out, int out_size)
{
    const float* node_emb = (const float*)d_in[0];
    const float* edge_fea = (const float*)d_in[1];
    const float* noise    = (const float*)d_in[2];

    // Detect input ordering: setup_inputs dict order has src/dst (size E) at 3,4;
    // reference-signature order has w_src1 (size D*H) at 3 and src/dst at 15,16.
    const int* src; const int* dst; int base;
    if (in_sizes[3] == in_sizes[2]) { src = (const int*)d_in[3];  dst = (const int*)d_in[4];  base = 5; }
    else                            { src = (const int*)d_in[15]; dst = (const int*)d_in[16]; base = 3; }

    const float* w_src1 = (const float*)d_in[base + 0];
    const float* b_src1 = (const float*)d_in[base + 1];
    const float* w_src2 = (const float*)d_in[base + 2];
    const float* b_src2 = (const float*)d_in[base + 3];
    const float* w_dst1 = (const float*)d_in[base + 4];
    const float* b_dst1 = (const float*)d_in[base + 5];
    const float* w_dst2 = (const float*)d_in[base + 6];
    const float* b_dst2 = (const float*)d_in[base + 7];
    const float* w_edge1 = (const float*)d_in[base + 8];
    const float* b_edge1 = (const float*)d_in[base + 9];
    const float* w_edge2 = (const float*)d_in[base + 10];
    const float* b_edge2 = (const float*)d_in[base + 11];

    const int Hd = in_sizes[base + 1];            // 128
    const int D  = in_sizes[base + 0] / Hd;       // 256
    const int N  = in_sizes[0] / D;               // 50000
    const int E  = in_sizes[2];                   // 1600000
    (void)n_in;

    float* out = (float*)d_out;
    float* aug = (out_size > E) ? (out + 1) : out;

    constexpr int NODE_SMEM = (TE * 256 + 32 * Hh + Hh + Hh) * (int)sizeof(float); // 82944
    constexpr int EDGE_SMEM = (128 * 128 + TE * 128 + Hh + Hh) * (int)sizeof(float); // 99328
    cudaFuncSetAttribute(node_kernel, cudaFuncAttributeMaxDynamicSharedMemorySize, NODE_SMEM);
    cudaFuncSetAttribute(edge_kernel, cudaFuncAttributeMaxDynamicSharedMemorySize, EDGE_SMEM);

    zero_kernel<<<1, 1>>>();

    int nodeTiles = (N + TE - 1) / TE;
    int nodeGrid = nodeTiles < 888 ? nodeTiles : 888;
    node_kernel<<<nodeGrid, THREADS, NODE_SMEM>>>(node_emb, N,
        w_src1, b_src1, w_src2, b_src2,
        w_dst1, b_dst1, w_dst2, b_dst2);

    int edgeTiles = (E + TE - 1) / TE;
    int edgeGrid = edgeTiles < 296 ? edgeTiles : 296;
    edge_kernel<<<edgeGrid, THREADS, EDGE_SMEM>>>(edge_fea, E,
        w_edge1, b_edge1, w_edge2, b_edge2,
        noise, src, dst, aug);

    if (out_size > E)
        finalize_kernel<<<1, 1>>>(out, 1.f / (float)E);
}

// round 3
// speedup vs baseline: 1.1922x; 1.1922x over previous
#include <cuda_runtime.h>
#include <cuda_bf16.h>
#include <stdint.h>
#include <math.h>

#define NMAX 50048

__device__ float g_ws[NMAX];
__device__ float g_wd[NMAX];
__device__ float g_sum;

__global__ void zero_kernel() { g_sum = 0.f; }
__global__ void finalize_kernel(float* out0, float invE) { *out0 = 1.f - g_sum * invE; }

__device__ __forceinline__ void cvt2(float x, float y, uint32_t& hi, uint32_t& lo) {
    __nv_bfloat16 hx = __float2bfloat16(x);
    __nv_bfloat16 hy = __float2bfloat16(y);
    float rx = x - __bfloat162float(hx);
    float ry = y - __bfloat162float(hy);
    __nv_bfloat162 H(hx, hy);
    __nv_bfloat162 L(__float2bfloat16(rx), __float2bfloat16(ry));
    hi = *reinterpret_cast<uint32_t*>(&H);
    lo = *reinterpret_cast<uint32_t*>(&L);
}

__device__ __forceinline__ void mma16816(float* c, const uint32_t* a, uint32_t b0, uint32_t b1) {
    asm volatile(
        "mma.sync.aligned.m16n8k16.row.col.f32.bf16.bf16.f32 "
        "{%0,%1,%2,%3}, {%4,%5,%6,%7}, {%8,%9}, {%0,%1,%2,%3};\n"
        : "+f"(c[0]), "+f"(c[1]), "+f"(c[2]), "+f"(c[3])
        : "r"(a[0]), "r"(a[1]), "r"(a[2]), "r"(a[3]), "r"(b0), "r"(b1));
}

// A stride fixed at 272 B (136 bf16). B stride passed (272 edge / 528 node) — both ≡4 words mod 32.
__device__ __forceinline__ void gemm_pass(float (&c)[2][8][4],
    const char* sA, const char* sB, int sbStride, int kts,
    int warp_m, int warp_n, int gid, int tg)
{
    #pragma unroll 2
    for (int kt = 0; kt < kts; ++kt) {
        uint32_t a[2][4];
        #pragma unroll
        for (int mt = 0; mt < 2; ++mt) {
            const char* p = sA + (warp_m + mt * 16 + gid) * 272 + kt * 32 + tg * 4;
            a[mt][0] = *(const uint32_t*)(p);
            a[mt][1] = *(const uint32_t*)(p + 8 * 272);
            a[mt][2] = *(const uint32_t*)(p + 16);
            a[mt][3] = *(const uint32_t*)(p + 8 * 272 + 16);
        }
        #pragma unroll
        for (int nt = 0; nt < 8; ++nt) {
            const char* q = sB + (warp_n + nt * 8 + gid) * sbStride + kt * 32 + tg * 4;
            uint32_t b0 = *(const uint32_t*)(q);
            uint32_t b1 = *(const uint32_t*)(q + 16);
            mma16816(c[0][nt], a[0], b0, b1);
            mma16816(c[1][nt], a[1], b0, b1);
        }
    }
}

// ---------------- smem layouts ----------------
// Edge: BtH 0 (34816), BtL 34816, A[4 planes] 69632.. (4*34816), B1 208896, W2 209408, RED 209920
#define E_BTH 0
#define E_BTL 34816
#define E_A   69632
#define E_B1  208896
#define E_W2  209408
#define E_RED 209920
#define EDGE_SMEM 210432
// Node: BtH 0 (67584), BtL 67584, AH 135168, AL 169984, B1 204800, W2 205312, RED 205824
#define N_BTH 0
#define N_BTL 67584
#define N_AH  135168
#define N_AL  169984
#define N_B1  204800
#define N_W2  205312
#define N_RED 205824
#define NODE_SMEM 206336

// ======================= NODE MLPs =======================
__global__ void __launch_bounds__(256, 1)
node_tc(const float* __restrict__ X, int N,
        const float* __restrict__ Ws1, const float* __restrict__ bs1,
        const float* __restrict__ ws2, const float* __restrict__ bs2,
        const float* __restrict__ Wd1, const float* __restrict__ bd1,
        const float* __restrict__ wd2, const float* __restrict__ bd2)
{
    extern __shared__ char smem[];
    const int tid = threadIdx.x;
    const int wid = tid >> 5, lane = tid & 31;
    const int gid = lane >> 2, tg = lane & 3;
    const int warp_m = (wid >> 1) * 32, warp_n = (wid & 1) * 64;

    const float* W1  = blockIdx.y ? Wd1 : Ws1;
    const float* b1g = blockIdx.y ? bd1 : bs1;
    const float* w2g = blockIdx.y ? wd2 : ws2;
    const float* b2g = blockIdx.y ? bd2 : bs2;
    float* outp = blockIdx.y ? g_wd : g_ws;

    float* sB1 = (float*)(smem + N_B1);
    float* sW2 = (float*)(smem + N_W2);
    float* sRed = (float*)(smem + N_RED);

    // build Bt[n][k] hi/lo, stride 528 B. W1 is [K=256][N=128].
    for (int idx = tid; idx < 256 * 128; idx += 256) {
        int n = idx & 127, k = idx >> 7;
        float w = W1[idx];
        __nv_bfloat16 h = __float2bfloat16(w);
        float r = w - __bfloat162float(h);
        int byte = n * 528 + k * 2;
        *(__nv_bfloat16*)(smem + N_BTH + byte) = h;
        *(__nv_bfloat16*)(smem + N_BTL + byte) = __float2bfloat16(r);
    }
    if (tid < 128) { sB1[tid] = b1g[tid]; sW2[tid] = w2g[tid]; }
    const float b2v = b2g[0];
    __syncthreads();

    const int numTiles = (N + 127) >> 7;
    for (int tile = blockIdx.x; tile < numTiles; tile += gridDim.x) {
        float c[2][8][4];
        #pragma unroll
        for (int i = 0; i < 2; i++)
            #pragma unroll
            for (int j = 0; j < 8; j++)
                #pragma unroll
                for (int q = 0; q < 4; q++) c[i][j][q] = 0.f;

        int row = tile * 128 + (tid >> 1);
        if (row >= N) row = N - 1;
        const float4* xp = (const float4*)(X + (size_t)row * 256);

        for (int kc = 0; kc < 2; ++kc) {
            __syncthreads();
            const int myrow = tid >> 1;
            #pragma unroll
            for (int i = 0; i < 16; ++i) {
                float4 v = xp[kc * 32 + (tid & 1) * 16 + i];
                uint32_t h0, l0, h1, l1;
                cvt2(v.x, v.y, h0, l0);
                cvt2(v.z, v.w, h1, l1);
                int byte = myrow * 272 + ((tid & 1) * 64 + i * 4) * 2;
                *(uint2*)(smem + N_AH + byte) = make_uint2(h0, h1);
                *(uint2*)(smem + N_AL + byte) = make_uint2(l0, l1);
            }
            __syncthreads();
            const char* Bh = smem + N_BTH + kc * 256;
            const char* Bl = smem + N_BTL + kc * 256;
            gemm_pass(c, smem + N_AH, Bh, 528, 8, warp_m, warp_n, gid, tg);
            gemm_pass(c, smem + N_AH, Bl, 528, 8, warp_m, warp_n, gid, tg);
            gemm_pass(c, smem + N_AL, Bh, 528, 8, warp_m, warp_n, gid, tg);
        }

        // epilogue
        float part[2][2] = {{0.f, 0.f}, {0.f, 0.f}};
        #pragma unroll
        for (int mt = 0; mt < 2; ++mt)
            #pragma unroll
            for (int nt = 0; nt < 8; ++nt) {
                int n0 = warp_n + nt * 8 + tg * 2;
                float b1a = sB1[n0], b1b = sB1[n0 + 1];
                float w2a = sW2[n0], w2b = sW2[n0 + 1];
                #pragma unroll
                for (int half = 0; half < 2; ++half) {
                    float h0 = c[mt][nt][half * 2] + b1a;     h0 = h0 > 0.f ? h0 : 0.01f * h0;
                    float h1 = c[mt][nt][half * 2 + 1] + b1b; h1 = h1 > 0.f ? h1 : 0.01f * h1;
                    part[mt][half] += h0 * w2a + h1 * w2b;
                }
            }
        #pragma unroll
        for (int mt = 0; mt < 2; ++mt)
            #pragma unroll
            for (int half = 0; half < 2; ++half) {
                part[mt][half] += __shfl_xor_sync(0xFFFFFFFFu, part[mt][half], 1);
                part[mt][half] += __shfl_xor_sync(0xFFFFFFFFu, part[mt][half], 2);
            }
        if ((wid & 1) && tg == 0) {
            #pragma unroll
            for (int mt = 0; mt < 2; ++mt)
                #pragma unroll
                for (int half = 0; half < 2; ++half)
                    sRed[warp_m + mt * 16 + half * 8 + gid] = part[mt][half];
        }
        __syncthreads();
        if (!(wid & 1) && tg == 0) {
            #pragma unroll
            for (int mt = 0; mt < 2; ++mt)
                #pragma unroll
                for (int half = 0; half < 2; ++half) {
                    int m = warp_m + mt * 16 + half * 8 + gid;
                    int nidx = tile * 128 + m;
                    if (nidx < N) outp[nidx] = part[mt][half] + sRed[m] + b2v;
                }
        }
        __syncthreads();
    }
}

// ======================= EDGE MLP (fused) =======================
__global__ void __launch_bounds__(256, 1)
edge_tc(const float* __restrict__ X, int E,
        const float* __restrict__ W1, const float* __restrict__ b1g,
        const float* __restrict__ w2g, const float* __restrict__ b2g,
        const float* __restrict__ noise, const int* __restrict__ src,
        const int* __restrict__ dst, float* __restrict__ aug)
{
    extern __shared__ char smem[];
    const int tid = threadIdx.x;
    const int wid = tid >> 5, lane = tid & 31;
    const int gid = lane >> 2, tg = lane & 3;
    const int warp_m = (wid >> 1) * 32, warp_n = (wid & 1) * 64;

    float* sB1 = (float*)(smem + E_B1);
    float* sW2 = (float*)(smem + E_W2);
    float* sRed = (float*)(smem + E_RED);

    // build Bt[n][k] hi/lo, stride 272 B. W1 is [K=128][N=128].
    for (int idx = tid; idx < 128 * 128; idx += 256) {
        int n = idx & 127, k = idx >> 7;
        float w = W1[idx];
        __nv_bfloat16 h = __float2bfloat16(w);
        float r = w - __bfloat162float(h);
        int byte = n * 272 + k * 2;
        *(__nv_bfloat16*)(smem + E_BTH + byte) = h;
        *(__nv_bfloat16*)(smem + E_BTL + byte) = __float2bfloat16(r);
    }
    if (tid < 128) { sB1[tid] = b1g[tid]; sW2[tid] = w2g[tid]; }
    const float b2v = b2g[0];
    __syncthreads();

    const int numTiles = (E + 127) >> 7;
    float localSum = 0.f;

    float4 st[16];
    int tile = blockIdx.x;
    bool have = tile < numTiles;
    if (have) {
        int row = tile * 128 + (tid >> 1);
        if (row >= E) row = E - 1;
        const float4* xp = (const float4*)(X + (size_t)row * 128);
        #pragma unroll
        for (int i = 0; i < 16; ++i) st[i] = xp[(tid & 1) * 16 + i];
    }

    int b = 0;
    while (have) {
        __syncthreads();
        // convert + store current stash into buffer b
        {
            const int myrow = tid >> 1;
            const char* AH = smem + E_A + (size_t)(b * 2) * 34816;
            const char* AL = AH + 34816;
            #pragma unroll
            for (int i = 0; i < 16; ++i) {
                uint32_t h0, l0, h1, l1;
                cvt2(st[i].x, st[i].y, h0, l0);
                cvt2(st[i].z, st[i].w, h1, l1);
                int byte = myrow * 272 + ((tid & 1) * 64 + i * 4) * 2;
                *(uint2*)(AH + byte) = make_uint2(h0, h1);
                *(uint2*)(AL + byte) = make_uint2(l0, l1);
            }
        }
        __syncthreads();

        // prefetch next tile (in flight during MMA)
        int nxt = tile + gridDim.x;
        bool haveN = nxt < numTiles;
        if (haveN) {
            int row = nxt * 128 + (tid >> 1);
            if (row >= E) row = E - 1;
            const float4* xp = (const float4*)(X + (size_t)row * 128);
            #pragma unroll
            for (int i = 0; i < 16; ++i) st[i] = xp[(tid & 1) * 16 + i];
        }

        float c[2][8][4];
        #pragma unroll
        for (int i = 0; i < 2; i++)
            #pragma unroll
            for (int j = 0; j < 8; j++)
                #pragma unroll
                for (int q = 0; q < 4; q++) c[i][j][q] = 0.f;

        const char* AH = smem + E_A + (size_t)(b * 2) * 34816;
        const char* AL = AH + 34816;
        gemm_pass(c, AH, smem + E_BTH, 272, 8, warp_m, warp_n, gid, tg);
        gemm_pass(c, AH, smem + E_BTL, 272, 8, warp_m, warp_n, gid, tg);
        gemm_pass(c, AL, smem + E_BTH, 272, 8, warp_m, warp_n, gid, tg);

        // epilogue
        float part[2][2] = {{0.f, 0.f}, {0.f, 0.f}};
        #pragma unroll
        for (int mt = 0; mt < 2; ++mt)
            #pragma unroll
            for (int nt = 0; nt < 8; ++nt) {
                int n0 = warp_n + nt * 8 + tg * 2;
                float b1a = sB1[n0], b1b = sB1[n0 + 1];
                float w2a = sW2[n0], w2b = sW2[n0 + 1];
                #pragma unroll
                for (int half = 0; half < 2; ++half) {
                    float h0 = c[mt][nt][half * 2] + b1a;     h0 = h0 > 0.f ? h0 : 0.01f * h0;
                    float h1 = c[mt][nt][half * 2 + 1] + b1b; h1 = h1 > 0.f ? h1 : 0.01f * h1;
                    part[mt][half] += h0 * w2a + h1 * w2b;
                }
            }
        #pragma unroll
        for (int mt = 0; mt < 2; ++mt)
            #pragma unroll
            for (int half = 0; half < 2; ++half) {
                part[mt][half] += __shfl_xor_sync(0xFFFFFFFFu, part[mt][half], 1);
                part[mt][half] += __shfl_xor_sync(0xFFFFFFFFu, part[mt][half], 2);
            }
        if ((wid & 1) && tg == 0) {
            #pragma unroll
            for (int mt = 0; mt < 2; ++mt)
                #pragma unroll
                for (int half = 0; half < 2; ++half)
                    sRed[warp_m + mt * 16 + half * 8 + gid] = part[mt][half];
        }
        __syncthreads();
        if (!(wid & 1) && tg == 0) {
            #pragma unroll
            for (int mt = 0; mt < 2; ++mt)
                #pragma unroll
                for (int half = 0; half < 2; ++half) {
                    int m = warp_m + mt * 16 + half * 8 + gid;
                    int e = tile * 128 + m;
                    if (e < E) {
                        float weight = part[mt][half] + sRed[m] + b2v
                                     + g_ws[src[e]] + g_wd[dst[e]];
                        float u = noise[e];
                        float eps = fmaf(2e-4f - 1.f, u, 1.f - 1e-4f);
                        float gate = (logf(eps) - log1pf(-eps) + weight) * 2.f;
                        float a = 1.f / (1.f + expf(-gate));
                        aug[e] = a;
                        localSum += a;
                    }
                }
        }

        tile = nxt;
        have = haveN;
        b ^= 1;
    }

    // block reduce localSum
    #pragma unroll
    for (int o = 16; o > 0; o >>= 1)
        localSum += __shfl_xor_sync(0xFFFFFFFFu, localSum, o);
    __shared__ float sPart[8];
    if (lane == 0) sPart[wid] = localSum;
    __syncthreads();
    if (tid == 0) {
        float s = 0.f;
        #pragma unroll
        for (int i = 0; i < 8; i++) s += sPart[i];
        atomicAdd(&g_sum, s);
    }
}

// ======================= host =======================
extern "C" void kernel_launch(void* const* d_in, const int* in_sizes, int n_in,
                              void* d_out, int out_size)
{
    const float* node_emb = (const float*)d_in[0];
    const float* edge_fea = (const float*)d_in[1];
    const float* noise    = (const float*)d_in[2];

    const int* src; const int* dst; int base;
    if (in_sizes[3] == in_sizes[2]) { src = (const int*)d_in[3];  dst = (const int*)d_in[4];  base = 5; }
    else                            { src = (const int*)d_in[15]; dst = (const int*)d_in[16]; base = 3; }

    const float* w_src1 = (const float*)d_in[base + 0];
    const float* b_src1 = (const float*)d_in[base + 1];
    const float* w_src2 = (const float*)d_in[base + 2];
    const float* b_src2 = (const float*)d_in[base + 3];
    const float* w_dst1 = (const float*)d_in[base + 4];
    const float* b_dst1 = (const float*)d_in[base + 5];
    const float* w_dst2 = (const float*)d_in[base + 6];
    const float* b_dst2 = (const float*)d_in[base + 7];
    const float* w_edge1 = (const float*)d_in[base + 8];
    const float* b_edge1 = (const float*)d_in[base + 9];
    const float* w_edge2 = (const float*)d_in[base + 10];
    const float* b_edge2 = (const float*)d_in[base + 11];

    const int Hd = in_sizes[base + 1];            // 128
    const int D  = in_sizes[base + 0] / Hd;       // 256
    const int N  = in_sizes[0] / D;               // 50000
    const int E  = in_sizes[2];                   // 1600000
    (void)n_in;

    float* out = (float*)d_out;
    float* aug = (out_size > E) ? (out + 1) : out;

    cudaFuncSetAttribute(node_tc, cudaFuncAttributeMaxDynamicSharedMemorySize, NODE_SMEM);
    cudaFuncSetAttribute(edge_tc, cudaFuncAttributeMaxDynamicSharedMemorySize, EDGE_SMEM);

    zero_kernel<<<1, 1>>>();

    int nTiles = (N + 127) / 128;
    dim3 ngrid(nTiles < 148 ? nTiles : 148, 2);
    node_tc<<<ngrid, 256, NODE_SMEM>>>(node_emb, N,
        w_src1, b_src1, w_src2, b_src2,
        w_dst1, b_dst1, w_dst2, b_dst2);

    int eTiles = (E + 127) / 128;
    int egrid = eTiles < 148 ? eTiles : 148;
    edge_tc<<<egrid, 256, EDGE_SMEM>>>(edge_fea, E,
        w_edge1, b_edge1, w_edge2, b_edge2,
        noise, src, dst, aug);

    if (out_size > E)
        finalize_kernel<<<1, 1>>>(out, 1.f / (float)E);
}

// round 4
// speedup vs baseline: 1.5512x; 1.3011x over previous
#include <cuda_runtime.h>
#include <cuda_bf16.h>
#include <stdint.h>
#include <math.h>

#define NMAX 50048

__device__ float g_ws[NMAX];
__device__ float g_wd[NMAX];
__device__ float g_sum;

__global__ void zero_kernel() { g_sum = 0.f; }
__global__ void finalize_kernel(float* out0, float invE) { *out0 = 1.f - g_sum * invE; }

__device__ __forceinline__ uint32_t smem_u32(const void* p) {
    uint32_t a;
    asm("{ .reg .u64 t; cvta.to.shared.u64 t, %1; cvt.u32.u64 %0, t; }" : "=r"(a) : "l"(p));
    return a;
}

__device__ __forceinline__ void cvt2(float x, float y, uint32_t& hi, uint32_t& lo) {
    __nv_bfloat16 hx = __float2bfloat16(x);
    __nv_bfloat16 hy = __float2bfloat16(y);
    float rx = x - __bfloat162float(hx);
    float ry = y - __bfloat162float(hy);
    __nv_bfloat162 H(hx, hy);
    __nv_bfloat162 L(__float2bfloat16(rx), __float2bfloat16(ry));
    hi = *reinterpret_cast<uint32_t*>(&H);
    lo = *reinterpret_cast<uint32_t*>(&L);
}

__device__ __forceinline__ void ldsm4(uint32_t* r, uint32_t addr) {
    asm volatile("ldmatrix.sync.aligned.m8n8.x4.shared.b16 {%0,%1,%2,%3}, [%4];"
        : "=r"(r[0]), "=r"(r[1]), "=r"(r[2]), "=r"(r[3]) : "r"(addr));
}

__device__ __forceinline__ void mma_bf16(float* c, const uint32_t* a, uint32_t b0, uint32_t b1) {
    asm volatile(
        "mma.sync.aligned.m16n8k16.row.col.f32.bf16.bf16.f32 "
        "{%0,%1,%2,%3}, {%4,%5,%6,%7}, {%8,%9}, {%0,%1,%2,%3};\n"
        : "+f"(c[0]), "+f"(c[1]), "+f"(c[2]), "+f"(c[3])
        : "r"(a[0]), "r"(a[1]), "r"(a[2]), "r"(a[3]), "r"(b0), "r"(b1));
}

// One k16 step of all 3 split passes (AhBh + AhBl + AlBh).
// aHi/aLo/bHi/bLo are lane-resolved smem addresses at this kt.
__device__ __forceinline__ void k_step(float (&c)[2][4][4],
    uint32_t aHi, uint32_t aLo, uint32_t bHi, uint32_t bLo, int bNpStride)
{
    uint32_t ah[2][4], al[2][4], bh[2][4], bl[2][4];
    ldsm4(ah[0], aHi);           ldsm4(ah[1], aHi + 4352);
    ldsm4(al[0], aLo);           ldsm4(al[1], aLo + 4352);
    ldsm4(bh[0], bHi);           ldsm4(bh[1], bHi + bNpStride);
    ldsm4(bl[0], bLo);           ldsm4(bl[1], bLo + bNpStride);
    #pragma unroll
    for (int mt = 0; mt < 2; ++mt)
        #pragma unroll
        for (int np = 0; np < 2; ++np)
            #pragma unroll
            for (int s = 0; s < 2; ++s) {
                float* cc = c[mt][np * 2 + s];
                mma_bf16(cc, ah[mt], bh[np][2 * s], bh[np][2 * s + 1]);
                mma_bf16(cc, ah[mt], bl[np][2 * s], bl[np][2 * s + 1]);
                mma_bf16(cc, al[mt], bh[np][2 * s], bh[np][2 * s + 1]);
            }
}

// ---------------- smem layouts (A planes stride 272 B; edge B stride 272, node B stride 528)
#define E_BTH 0
#define E_BTL 34816
#define E_A   69632
#define E_B1  208896
#define E_W2  209408
#define E_RED 209920
#define EDGE_SMEM 211456

#define N_BTH 0
#define N_BTL 67584
#define N_AH  135168
#define N_AL  169984
#define N_B1  204800
#define N_W2  205312
#define N_RED 205824
#define NODE_SMEM 207360

// ======================= NODE MLPs =======================
__global__ void __launch_bounds__(512, 1)
node_tc(const float* __restrict__ X, int N,
        const float* __restrict__ Ws1, const float* __restrict__ bs1,
        const float* __restrict__ ws2, const float* __restrict__ bs2,
        const float* __restrict__ Wd1, const float* __restrict__ bd1,
        const float* __restrict__ wd2, const float* __restrict__ bd2)
{
    extern __shared__ char smem[];
    const uint32_t sb = smem_u32(smem);
    const int tid = threadIdx.x;
    const int wid = tid >> 5, lane = tid & 31;
    const int warp_m = (wid >> 2) * 32, warp_n = (wid & 3) * 32;
    const int nwid = wid & 3;

    const float* W1  = blockIdx.y ? Wd1 : Ws1;
    const float* b1g = blockIdx.y ? bd1 : bs1;
    const float* w2g = blockIdx.y ? wd2 : ws2;
    const float* b2g = blockIdx.y ? bd2 : bs2;
    float* outp = blockIdx.y ? g_wd : g_ws;

    float* sB1 = (float*)(smem + N_B1);
    float* sW2 = (float*)(smem + N_W2);
    float* sRed = (float*)(smem + N_RED);

    // Bt[n][k] hi/lo, stride 528. W1 is [K=256][N=128].
    for (int idx = tid; idx < 256 * 128; idx += 512) {
        int n = idx & 127, k = idx >> 7;
        float w = W1[idx];
        __nv_bfloat16 h = __float2bfloat16(w);
        float r = w - __bfloat162float(h);
        int byte = n * 528 + k * 2;
        *(__nv_bfloat16*)(smem + N_BTH + byte) = h;
        *(__nv_bfloat16*)(smem + N_BTL + byte) = __float2bfloat16(r);
    }
    if (tid < 128) { sB1[tid] = b1g[tid]; sW2[tid] = w2g[tid]; }
    const float b2v = b2g[0];
    __syncthreads();

    // lane-resolved ldmatrix base offsets
    const uint32_t aLaneOff = (uint32_t)((warp_m + (lane & 15)) * 272 + (lane >> 4) * 16);
    const uint32_t bLaneRow = (uint32_t)(warp_n + (lane & 7) + ((lane >> 4) << 3));
    const uint32_t bLaneOff = bLaneRow * 528 + (((uint32_t)lane >> 3) & 1) * 16;

    const int numTiles = (N + 127) >> 7;
    for (int tile = blockIdx.x; tile < numTiles; tile += gridDim.x) {
        float c[2][4][4];
        #pragma unroll
        for (int i = 0; i < 2; i++)
            #pragma unroll
            for (int j = 0; j < 4; j++)
                #pragma unroll
                for (int q = 0; q < 4; q++) c[i][j][q] = 0.f;

        int row = tile * 128 + (tid >> 2);
        if (row >= N) row = N - 1;
        const float4* xp = (const float4*)(X + (size_t)row * 256);
        const int q = tid & 3;
        const int myrow = tid >> 2;

        for (int kc = 0; kc < 2; ++kc) {
            __syncthreads();   // protect A buffer from previous gemm reads
            #pragma unroll
            for (int i = 0; i < 8; ++i) {
                float4 v = xp[kc * 32 + q * 8 + i];
                uint32_t h0, l0, h1, l1;
                cvt2(v.x, v.y, h0, l0);
                cvt2(v.z, v.w, h1, l1);
                int byte = myrow * 272 + (q * 32 + i * 4) * 2;
                *(uint2*)(smem + N_AH + byte) = make_uint2(h0, h1);
                *(uint2*)(smem + N_AL + byte) = make_uint2(l0, l1);
            }
            __syncthreads();
            const uint32_t aHi = sb + N_AH + aLaneOff;
            const uint32_t aLo = sb + N_AL + aLaneOff;
            const uint32_t bHi = sb + N_BTH + bLaneOff + kc * 256;
            const uint32_t bLo = sb + N_BTL + bLaneOff + kc * 256;
            #pragma unroll
            for (int kt = 0; kt < 8; ++kt)
                k_step(c, aHi + kt * 32, aLo + kt * 32, bHi + kt * 32, bLo + kt * 32, 16 * 528);
        }

        // epilogue
        float part[2][2] = {{0.f, 0.f}, {0.f, 0.f}};
        #pragma unroll
        for (int mt = 0; mt < 2; ++mt)
            #pragma unroll
            for (int nt = 0; nt < 4; ++nt) {
                int n0 = warp_n + nt * 8 + (lane & 3) * 2;
                float b1a = sB1[n0], b1b = sB1[n0 + 1];
                float w2a = sW2[n0], w2b = sW2[n0 + 1];
                #pragma unroll
                for (int half = 0; half < 2; ++half) {
                    float h0 = c[mt][nt][half * 2] + b1a;     h0 = h0 > 0.f ? h0 : 0.01f * h0;
                    float h1 = c[mt][nt][half * 2 + 1] + b1b; h1 = h1 > 0.f ? h1 : 0.01f * h1;
                    part[mt][half] += h0 * w2a + h1 * w2b;
                }
            }
        #pragma unroll
        for (int mt = 0; mt < 2; ++mt)
            #pragma unroll
            for (int half = 0; half < 2; ++half) {
                part[mt][half] += __shfl_xor_sync(0xFFFFFFFFu, part[mt][half], 1);
                part[mt][half] += __shfl_xor_sync(0xFFFFFFFFu, part[mt][half], 2);
            }
        if (nwid && (lane & 3) == 0) {
            #pragma unroll
            for (int mt = 0; mt < 2; ++mt)
                #pragma unroll
                for (int half = 0; half < 2; ++half) {
                    int m = warp_m + mt * 16 + half * 8 + (lane >> 2);
                    sRed[(nwid - 1) * 128 + m] = part[mt][half];
                }
        }
        __syncthreads();
        if (nwid == 0 && (lane & 3) == 0) {
            #pragma unroll
            for (int mt = 0; mt < 2; ++mt)
                #pragma unroll
                for (int half = 0; half < 2; ++half) {
                    int m = warp_m + mt * 16 + half * 8 + (lane >> 2);
                    int nidx = tile * 128 + m;
                    if (nidx < N)
                        outp[nidx] = part[mt][half] + sRed[m] + sRed[128 + m] + sRed[256 + m] + b2v;
                }
        }
        __syncthreads();
    }
}

// ======================= EDGE MLP (fused) =======================
__global__ void __launch_bounds__(512, 1)
edge_tc(const float* __restrict__ X, int E,
        const float* __restrict__ W1, const float* __restrict__ b1g,
        const float* __restrict__ w2g, const float* __restrict__ b2g,
        const float* __restrict__ noise, const int* __restrict__ src,
        const int* __restrict__ dst, float* __restrict__ aug)
{
    extern __shared__ char smem[];
    const uint32_t sb = smem_u32(smem);
    const int tid = threadIdx.x;
    const int wid = tid >> 5, lane = tid & 31;
    const int warp_m = (wid >> 2) * 32, warp_n = (wid & 3) * 32;
    const int nwid = wid & 3;

    float* sB1 = (float*)(smem + E_B1);
    float* sW2 = (float*)(smem + E_W2);
    float* sRed = (float*)(smem + E_RED);

    // Bt[n][k] hi/lo, stride 272. W1 is [K=128][N=128].
    for (int idx = tid; idx < 128 * 128; idx += 512) {
        int n = idx & 127, k = idx >> 7;
        float w = W1[idx];
        __nv_bfloat16 h = __float2bfloat16(w);
        float r = w - __bfloat162float(h);
        int byte = n * 272 + k * 2;
        *(__nv_bfloat16*)(smem + E_BTH + byte) = h;
        *(__nv_bfloat16*)(smem + E_BTL + byte) = __float2bfloat16(r);
    }
    if (tid < 128) { sB1[tid] = b1g[tid]; sW2[tid] = w2g[tid]; }
    const float b2v = b2g[0];
    __syncthreads();

    const uint32_t aLaneOff = (uint32_t)((warp_m + (lane & 15)) * 272 + (lane >> 4) * 16);
    const uint32_t bLaneRow = (uint32_t)(warp_n + (lane & 7) + ((lane >> 4) << 3));
    const uint32_t bLaneOff = bLaneRow * 272 + (((uint32_t)lane >> 3) & 1) * 16;
    const uint32_t bHi = sb + E_BTH + bLaneOff;
    const uint32_t bLo = sb + E_BTL + bLaneOff;

    const int numTiles = (E + 127) >> 7;
    float localSum = 0.f;

    const int q = tid & 3;
    const int myrow = tid >> 2;

    float4 st[8];
    int tile = blockIdx.x;
    bool have = tile < numTiles;
    if (have) {
        int row = tile * 128 + myrow;
        if (row >= E) row = E - 1;
        const float4* xp = (const float4*)(X + (size_t)row * 128);
        #pragma unroll
        for (int i = 0; i < 8; ++i) st[i] = xp[q * 8 + i];
    }

    int b = 0;
    while (have) {
        // convert stash into buffer b
        {
            char* AH = smem + E_A + b * 69632;
            char* AL = AH + 34816;
            #pragma unroll
            for (int i = 0; i < 8; ++i) {
                uint32_t h0, l0, h1, l1;
                cvt2(st[i].x, st[i].y, h0, l0);
                cvt2(st[i].z, st[i].w, h1, l1);
                int byte = myrow * 272 + (q * 32 + i * 4) * 2;
                *(uint2*)(AH + byte) = make_uint2(h0, h1);
                *(uint2*)(AL + byte) = make_uint2(l0, l1);
            }
        }
        __syncthreads();

        // prefetch next tile (LDG in flight during MMA)
        int nxt = tile + gridDim.x;
        bool haveN = nxt < numTiles;
        if (haveN) {
            int row = nxt * 128 + myrow;
            if (row >= E) row = E - 1;
            const float4* xp = (const float4*)(X + (size_t)row * 128);
            #pragma unroll
            for (int i = 0; i < 8; ++i) st[i] = xp[q * 8 + i];
        }

        float c[2][4][4];
        #pragma unroll
        for (int i = 0; i < 2; i++)
            #pragma unroll
            for (int j = 0; j < 4; j++)
                #pragma unroll
                for (int qq = 0; qq < 4; qq++) c[i][j][qq] = 0.f;

        const uint32_t aHi = sb + E_A + b * 69632 + aLaneOff;
        const uint32_t aLo = aHi + 34816;
        #pragma unroll
        for (int kt = 0; kt < 8; ++kt)
            k_step(c, aHi + kt * 32, aLo + kt * 32, bHi + kt * 32, bLo + kt * 32, 16 * 272);

        // epilogue
        float part[2][2] = {{0.f, 0.f}, {0.f, 0.f}};
        #pragma unroll
        for (int mt = 0; mt < 2; ++mt)
            #pragma unroll
            for (int nt = 0; nt < 4; ++nt) {
                int n0 = warp_n + nt * 8 + (lane & 3) * 2;
                float b1a = sB1[n0], b1b = sB1[n0 + 1];
                float w2a = sW2[n0], w2b = sW2[n0 + 1];
                #pragma unroll
                for (int half = 0; half < 2; ++half) {
                    float h0 = c[mt][nt][half * 2] + b1a;     h0 = h0 > 0.f ? h0 : 0.01f * h0;
                    float h1 = c[mt][nt][half * 2 + 1] + b1b; h1 = h1 > 0.f ? h1 : 0.01f * h1;
                    part[mt][half] += h0 * w2a + h1 * w2b;
                }
            }
        #pragma unroll
        for (int mt = 0; mt < 2; ++mt)
            #pragma unroll
            for (int half = 0; half < 2; ++half) {
                part[mt][half] += __shfl_xor_sync(0xFFFFFFFFu, part[mt][half], 1);
                part[mt][half] += __shfl_xor_sync(0xFFFFFFFFu, part[mt][half], 2);
            }
        if (nwid && (lane & 3) == 0) {
            #pragma unroll
            for (int mt = 0; mt < 2; ++mt)
                #pragma unroll
                for (int half = 0; half < 2; ++half) {
                    int m = warp_m + mt * 16 + half * 8 + (lane >> 2);
                    sRed[(nwid - 1) * 128 + m] = part[mt][half];
                }
        }
        __syncthreads();
        if (nwid == 0 && (lane & 3) == 0) {
            #pragma unroll
            for (int mt = 0; mt < 2; ++mt)
                #pragma unroll
                for (int half = 0; half < 2; ++half) {
                    int m = warp_m + mt * 16 + half * 8 + (lane >> 2);
                    int e = tile * 128 + m;
                    if (e < E) {
                        float weight = part[mt][half] + sRed[m] + sRed[128 + m] + sRed[256 + m]
                                     + b2v + g_ws[src[e]] + g_wd[dst[e]];
                        float u = noise[e];
                        float eps = fmaf(2e-4f - 1.f, u, 1.f - 1e-4f);
                        float gate = (logf(eps) - log1pf(-eps) + weight) * 2.f;
                        float a = 1.f / (1.f + expf(-gate));
                        aug[e] = a;
                        localSum += a;
                    }
                }
        }
        __syncthreads();

        tile = nxt;
        have = haveN;
        b ^= 1;
    }

    // block reduce localSum
    #pragma unroll
    for (int o = 16; o > 0; o >>= 1)
        localSum += __shfl_xor_sync(0xFFFFFFFFu, localSum, o);
    __shared__ float sPart[16];
    if (lane == 0) sPart[wid] = localSum;
    __syncthreads();
    if (tid == 0) {
        float s = 0.f;
        #pragma unroll
        for (int i = 0; i < 16; i++) s += sPart[i];
        atomicAdd(&g_sum, s);
    }
}

// ======================= host =======================
extern "C" void kernel_launch(void* const* d_in, const int* in_sizes, int n_in,
                              void* d_out, int out_size)
{
    const float* node_emb = (const float*)d_in[0];
    const float* edge_fea = (const float*)d_in[1];
    const float* noise    = (const float*)d_in[2];

    const int* src; const int* dst; int base;
    if (in_sizes[3] == in_sizes[2]) { src = (const int*)d_in[3];  dst = (const int*)d_in[4];  base = 5; }
    else                            { src = (const int*)d_in[15]; dst = (const int*)d_in[16]; base = 3; }

    const float* w_src1 = (const float*)d_in[base + 0];
    const float* b_src1 = (const float*)d_in[base + 1];
    const float* w_src2 = (const float*)d_in[base + 2];
    const float* b_src2 = (const float*)d_in[base + 3];
    const float* w_dst1 = (const float*)d_in[base + 4];
    const float* b_dst1 = (const float*)d_in[base + 5];
    const float* w_dst2 = (const float*)d_in[base + 6];
    const float* b_dst2 = (const float*)d_in[base + 7];
    const float* w_edge1 = (const float*)d_in[base + 8];
    const float* b_edge1 = (const float*)d_in[base + 9];
    const float* w_edge2 = (const float*)d_in[base + 10];
    const float* b_edge2 = (const float*)d_in[base + 11];

    const int Hd = in_sizes[base + 1];            // 128
    const int D  = in_sizes[base + 0] / Hd;       // 256
    const int N  = in_sizes[0] / D;               // 50000
    const int E  = in_sizes[2];                   // 1600000
    (void)n_in;

    float* out = (float*)d_out;
    float* aug = (out_size > E) ? (out + 1) : out;

    cudaFuncSetAttribute(node_tc, cudaFuncAttributeMaxDynamicSharedMemorySize, NODE_SMEM);
    cudaFuncSetAttribute(edge_tc, cudaFuncAttributeMaxDynamicSharedMemorySize, EDGE_SMEM);

    zero_kernel<<<1, 1>>>();

    int nTiles = (N + 127) / 128;
    dim3 ngrid(nTiles < 148 ? nTiles : 148, 2);
    node_tc<<<ngrid, 512, NODE_SMEM>>>(node_emb, N,
        w_src1, b_src1, w_src2, b_src2,
        w_dst1, b_dst1, w_dst2, b_dst2);

    int eTiles = (E + 127) / 128;
    int egrid = eTiles < 148 ? eTiles : 148;
    edge_tc<<<egrid, 512, EDGE_SMEM>>>(edge_fea, E,
        w_edge1, b_edge1, w_edge2, b_edge2,
        noise, src, dst, aug);

    if (out_size > E)
        finalize_kernel<<<1, 1>>>(out, 1.f / (float)E);
}

// round 5
// speedup vs baseline: 1.8752x; 1.2089x over previous
#include <cuda_runtime.h>
#include <cuda_bf16.h>
#include <cuda_fp16.h>
#include <stdint.h>
#include <math.h>

#define NMAX 50048

__device__ float g_ws[NMAX];
__device__ float g_wd[NMAX];
__device__ float g_sum;

__global__ void zero_kernel() { g_sum = 0.f; }
__global__ void finalize_kernel(float* out0, float invE) { *out0 = 1.f - g_sum * invE; }

__device__ __forceinline__ uint32_t smem_u32(const void* p) {
    uint32_t a;
    asm("{ .reg .u64 t; cvta.to.shared.u64 t, %1; cvt.u32.u64 %0, t; }" : "=r"(a) : "l"(p));
    return a;
}

__device__ __forceinline__ void cvt2_bf(float x, float y, uint32_t& hi, uint32_t& lo) {
    __nv_bfloat16 hx = __float2bfloat16(x);
    __nv_bfloat16 hy = __float2bfloat16(y);
    float rx = x - __bfloat162float(hx);
    float ry = y - __bfloat162float(hy);
    __nv_bfloat162 H(hx, hy);
    __nv_bfloat162 L(__float2bfloat16(rx), __float2bfloat16(ry));
    hi = *reinterpret_cast<uint32_t*>(&H);
    lo = *reinterpret_cast<uint32_t*>(&L);
}

__device__ __forceinline__ void ldsm4(uint32_t* r, uint32_t addr) {
    asm volatile("ldmatrix.sync.aligned.m8n8.x4.shared.b16 {%0,%1,%2,%3}, [%4];"
        : "=r"(r[0]), "=r"(r[1]), "=r"(r[2]), "=r"(r[3]) : "r"(addr));
}

__device__ __forceinline__ void mma_bf16(float* c, const uint32_t* a, uint32_t b0, uint32_t b1) {
    asm volatile(
        "mma.sync.aligned.m16n8k16.row.col.f32.bf16.bf16.f32 "
        "{%0,%1,%2,%3}, {%4,%5,%6,%7}, {%8,%9}, {%0,%1,%2,%3};\n"
        : "+f"(c[0]), "+f"(c[1]), "+f"(c[2]), "+f"(c[3])
        : "r"(a[0]), "r"(a[1]), "r"(a[2]), "r"(a[3]), "r"(b0), "r"(b1));
}
__device__ __forceinline__ void mma_f16(float* c, const uint32_t* a, uint32_t b0, uint32_t b1) {
    asm volatile(
        "mma.sync.aligned.m16n8k16.row.col.f32.f16.f16.f32 "
        "{%0,%1,%2,%3}, {%4,%5,%6,%7}, {%8,%9}, {%0,%1,%2,%3};\n"
        : "+f"(c[0]), "+f"(c[1]), "+f"(c[2]), "+f"(c[3])
        : "r"(a[0]), "r"(a[1]), "r"(a[2]), "r"(a[3]), "r"(b0), "r"(b1));
}

// -------- node k-step: bf16 3-pass (AhBh + AhBl + AlBh) --------
__device__ __forceinline__ void k_step_n(float (&c)[2][4][4],
    uint32_t aHi, uint32_t aLo, uint32_t bHi, uint32_t bLo, int bNpStride)
{
    uint32_t ah[2][4], al[2][4], bh[2][4], bl[2][4];
    ldsm4(ah[0], aHi);           ldsm4(ah[1], aHi + 4352);
    ldsm4(al[0], aLo);           ldsm4(al[1], aLo + 4352);
    ldsm4(bh[0], bHi);           ldsm4(bh[1], bHi + bNpStride);
    ldsm4(bl[0], bLo);           ldsm4(bl[1], bLo + bNpStride);
    #pragma unroll
    for (int mt = 0; mt < 2; ++mt)
        #pragma unroll
        for (int np = 0; np < 2; ++np)
            #pragma unroll
            for (int s = 0; s < 2; ++s) {
                float* cc = c[mt][np * 2 + s];
                mma_bf16(cc, ah[mt], bh[np][2 * s], bh[np][2 * s + 1]);
                mma_bf16(cc, ah[mt], bl[np][2 * s], bl[np][2 * s + 1]);
                mma_bf16(cc, al[mt], bh[np][2 * s], bh[np][2 * s + 1]);
            }
}

// -------- edge k-step: fp16 2-pass (Ah·Bh + Ah·Bl), dependent MMAs spaced 8 apart --------
__device__ __forceinline__ void k_step_e(float (&c)[2][4][4],
    uint32_t aHi, uint32_t bHi, uint32_t bLo, int bNpStride)
{
    uint32_t ah[2][4], bh[2][4], bl[2][4];
    ldsm4(ah[0], aHi);           ldsm4(ah[1], aHi + 4352);
    ldsm4(bh[0], bHi);           ldsm4(bh[1], bHi + bNpStride);
    ldsm4(bl[0], bLo);           ldsm4(bl[1], bLo + bNpStride);
    #pragma unroll
    for (int mt = 0; mt < 2; ++mt)
        #pragma unroll
        for (int np = 0; np < 2; ++np)
            #pragma unroll
            for (int s = 0; s < 2; ++s)
                mma_f16(c[mt][np * 2 + s], ah[mt], bh[np][2 * s], bh[np][2 * s + 1]);
    #pragma unroll
    for (int mt = 0; mt < 2; ++mt)
        #pragma unroll
        for (int np = 0; np < 2; ++np)
            #pragma unroll
            for (int s = 0; s < 2; ++s)
                mma_f16(c[mt][np * 2 + s], ah[mt], bl[np][2 * s], bl[np][2 * s + 1]);
}

// ---------------- smem layouts ----------------
// Edge: BtH 0, BtL 34816, A 2 bufs (hi only) 69632.., B1 139264, W2 139776, RED 140288
#define E_BTH 0
#define E_BTL 34816
#define E_A   69632
#define E_B1  139264
#define E_W2  139776
#define E_RED 140288
#define EDGE_SMEM 142336

#define N_BTH 0
#define N_BTL 67584
#define N_AH  135168
#define N_AL  169984
#define N_B1  204800
#define N_W2  205312
#define N_RED 205824
#define NODE_SMEM 207360

// ======================= NODE MLPs (bf16 3-pass, unchanged engine) =======================
__global__ void __launch_bounds__(512, 1)
node_tc(const float* __restrict__ X, int N,
        const float* __restrict__ Ws1, const float* __restrict__ bs1,
        const float* __restrict__ ws2, const float* __restrict__ bs2,
        const float* __restrict__ Wd1, const float* __restrict__ bd1,
        const float* __restrict__ wd2, const float* __restrict__ bd2)
{
    extern __shared__ char smem[];
    const uint32_t sb = smem_u32(smem);
    const int tid = threadIdx.x;
    const int wid = tid >> 5, lane = tid & 31;
    const int warp_m = (wid >> 2) * 32, warp_n = (wid & 3) * 32;
    const int nwid = wid & 3;

    const float* W1  = blockIdx.y ? Wd1 : Ws1;
    const float* b1g = blockIdx.y ? bd1 : bs1;
    const float* w2g = blockIdx.y ? wd2 : ws2;
    const float* b2g = blockIdx.y ? bd2 : bs2;
    float* outp = blockIdx.y ? g_wd : g_ws;

    float* sB1 = (float*)(smem + N_B1);
    float* sW2 = (float*)(smem + N_W2);
    float* sRed = (float*)(smem + N_RED);

    for (int idx = tid; idx < 256 * 128; idx += 512) {
        int n = idx & 127, k = idx >> 7;
        float w = W1[idx];
        __nv_bfloat16 h = __float2bfloat16(w);
        float r = w - __bfloat162float(h);
        int byte = n * 528 + k * 2;
        *(__nv_bfloat16*)(smem + N_BTH + byte) = h;
        *(__nv_bfloat16*)(smem + N_BTL + byte) = __float2bfloat16(r);
    }
    if (tid < 128) { sB1[tid] = b1g[tid]; sW2[tid] = w2g[tid]; }
    const float b2v = b2g[0];
    __syncthreads();

    const uint32_t aLaneOff = (uint32_t)((warp_m + (lane & 15)) * 272 + (lane >> 4) * 16);
    const uint32_t bLaneRow = (uint32_t)(warp_n + (lane & 7) + ((lane >> 4) << 3));
    const uint32_t bLaneOff = bLaneRow * 528 + (((uint32_t)lane >> 3) & 1) * 16;

    const int numTiles = (N + 127) >> 7;
    for (int tile = blockIdx.x; tile < numTiles; tile += gridDim.x) {
        float c[2][4][4];
        #pragma unroll
        for (int i = 0; i < 2; i++)
            #pragma unroll
            for (int j = 0; j < 4; j++)
                #pragma unroll
                for (int q = 0; q < 4; q++) c[i][j][q] = 0.f;

        int row = tile * 128 + (tid >> 2);
        if (row >= N) row = N - 1;
        const float4* xp = (const float4*)(X + (size_t)row * 256);
        const int q = tid & 3;
        const int myrow = tid >> 2;

        for (int kc = 0; kc < 2; ++kc) {
            __syncthreads();
            #pragma unroll
            for (int i = 0; i < 8; ++i) {
                float4 v = xp[kc * 32 + q * 8 + i];
                uint32_t h0, l0, h1, l1;
                cvt2_bf(v.x, v.y, h0, l0);
                cvt2_bf(v.z, v.w, h1, l1);
                int byte = myrow * 272 + (q * 32 + i * 4) * 2;
                *(uint2*)(smem + N_AH + byte) = make_uint2(h0, h1);
                *(uint2*)(smem + N_AL + byte) = make_uint2(l0, l1);
            }
            __syncthreads();
            const uint32_t aHi = sb + N_AH + aLaneOff;
            const uint32_t aLo = sb + N_AL + aLaneOff;
            const uint32_t bHi = sb + N_BTH + bLaneOff + kc * 256;
            const uint32_t bLo = sb + N_BTL + bLaneOff + kc * 256;
            #pragma unroll
            for (int kt = 0; kt < 8; ++kt)
                k_step_n(c, aHi + kt * 32, aLo + kt * 32, bHi + kt * 32, bLo + kt * 32, 16 * 528);
        }

        float part[2][2] = {{0.f, 0.f}, {0.f, 0.f}};
        #pragma unroll
        for (int mt = 0; mt < 2; ++mt)
            #pragma unroll
            for (int nt = 0; nt < 4; ++nt) {
                int n0 = warp_n + nt * 8 + (lane & 3) * 2;
                float b1a = sB1[n0], b1b = sB1[n0 + 1];
                float w2a = sW2[n0], w2b = sW2[n0 + 1];
                #pragma unroll
                for (int half = 0; half < 2; ++half) {
                    float h0 = c[mt][nt][half * 2] + b1a;     h0 = h0 > 0.f ? h0 : 0.01f * h0;
                    float h1 = c[mt][nt][half * 2 + 1] + b1b; h1 = h1 > 0.f ? h1 : 0.01f * h1;
                    part[mt][half] += h0 * w2a + h1 * w2b;
                }
            }
        #pragma unroll
        for (int mt = 0; mt < 2; ++mt)
            #pragma unroll
            for (int half = 0; half < 2; ++half) {
                part[mt][half] += __shfl_xor_sync(0xFFFFFFFFu, part[mt][half], 1);
                part[mt][half] += __shfl_xor_sync(0xFFFFFFFFu, part[mt][half], 2);
            }
        if (nwid && (lane & 3) == 0) {
            #pragma unroll
            for (int mt = 0; mt < 2; ++mt)
                #pragma unroll
                for (int half = 0; half < 2; ++half) {
                    int m = warp_m + mt * 16 + half * 8 + (lane >> 2);
                    sRed[(nwid - 1) * 128 + m] = part[mt][half];
                }
        }
        __syncthreads();
        if (nwid == 0 && (lane & 3) == 0) {
            #pragma unroll
            for (int mt = 0; mt < 2; ++mt)
                #pragma unroll
                for (int half = 0; half < 2; ++half) {
                    int m = warp_m + mt * 16 + half * 8 + (lane >> 2);
                    int nidx = tile * 128 + m;
                    if (nidx < N)
                        outp[nidx] = part[mt][half] + sRed[m] + sRed[128 + m] + sRed[256 + m] + b2v;
                }
        }
        __syncthreads();
    }
}

// ======================= EDGE MLP (fp16 2-pass, fused) =======================
__global__ void __launch_bounds__(512, 1)
edge_tc(const float* __restrict__ X, int E,
        const float* __restrict__ W1, const float* __restrict__ b1g,
        const float* __restrict__ w2g, const float* __restrict__ b2g,
        const float* __restrict__ noise, const int* __restrict__ src,
        const int* __restrict__ dst, float* __restrict__ aug)
{
    extern __shared__ char smem[];
    const uint32_t sb = smem_u32(smem);
    const int tid = threadIdx.x;
    const int wid = tid >> 5, lane = tid & 31;
    const int warp_m = (wid >> 2) * 32, warp_n = (wid & 3) * 32;
    const int nwid = wid & 3;

    float* sB1 = (float*)(smem + E_B1);
    float* sW2 = (float*)(smem + E_W2);
    float* sRed = (float*)(smem + E_RED);

    // Bt[n][k] fp16 hi/lo, stride 272. W1 is [K=128][N=128].
    for (int idx = tid; idx < 128 * 128; idx += 512) {
        int n = idx & 127, k = idx >> 7;
        float w = W1[idx];
        __half h = __float2half_rn(w);
        float r = w - __half2float(h);
        int byte = n * 272 + k * 2;
        *(__half*)(smem + E_BTH + byte) = h;
        *(__half*)(smem + E_BTL + byte) = __float2half_rn(r);
    }
    if (tid < 128) { sB1[tid] = b1g[tid]; sW2[tid] = w2g[tid]; }
    const float b2v = b2g[0];
    __syncthreads();

    const uint32_t aLaneOff = (uint32_t)((warp_m + (lane & 15)) * 272 + (lane >> 4) * 16);
    const uint32_t bLaneRow = (uint32_t)(warp_n + (lane & 7) + ((lane >> 4) << 3));
    const uint32_t bLaneOff = bLaneRow * 272 + (((uint32_t)lane >> 3) & 1) * 16;
    const uint32_t bHi = sb + E_BTH + bLaneOff;
    const uint32_t bLo = sb + E_BTL + bLaneOff;

    const int numTiles = (E + 127) >> 7;
    float localSum = 0.f;

    const int q = tid & 3;
    const int myrow = tid >> 2;

    float4 st[8];
    int tile = blockIdx.x;
    bool have = tile < numTiles;
    if (have) {
        int row = tile * 128 + myrow;
        if (row >= E) row = E - 1;
        const float4* xp = (const float4*)(X + (size_t)row * 128);
        #pragma unroll
        for (int i = 0; i < 8; ++i) st[i] = xp[q * 8 + i];
    }

    int b = 0;
    while (have) {
        // convert stash (fp16 hi only) into buffer b
        {
            char* AH = smem + E_A + b * 34816;
            #pragma unroll
            for (int i = 0; i < 8; ++i) {
                __half2 h0 = __floats2half2_rn(st[i].x, st[i].y);
                __half2 h1 = __floats2half2_rn(st[i].z, st[i].w);
                int byte = myrow * 272 + (q * 32 + i * 4) * 2;
                *(uint2*)(AH + byte) = make_uint2(*(uint32_t*)&h0, *(uint32_t*)&h1);
            }
        }
        __syncthreads();

        // prefetch next tile (LDG in flight during MMA)
        int nxt = tile + gridDim.x;
        bool haveN = nxt < numTiles;
        if (haveN) {
            int row = nxt * 128 + myrow;
            if (row >= E) row = E - 1;
            const float4* xp = (const float4*)(X + (size_t)row * 128);
            #pragma unroll
            for (int i = 0; i < 8; ++i) st[i] = xp[q * 8 + i];
        }

        float c[2][4][4];
        #pragma unroll
        for (int i = 0; i < 2; i++)
            #pragma unroll
            for (int j = 0; j < 4; j++)
                #pragma unroll
                for (int qq = 0; qq < 4; qq++) c[i][j][qq] = 0.f;

        const uint32_t aHi = sb + E_A + b * 34816 + aLaneOff;
        #pragma unroll
        for (int kt = 0; kt < 8; ++kt)
            k_step_e(c, aHi + kt * 32, bHi + kt * 32, bLo + kt * 32, 16 * 272);

        // epilogue
        float part[2][2] = {{0.f, 0.f}, {0.f, 0.f}};
        #pragma unroll
        for (int mt = 0; mt < 2; ++mt)
            #pragma unroll
            for (int nt = 0; nt < 4; ++nt) {
                int n0 = warp_n + nt * 8 + (lane & 3) * 2;
                float b1a = sB1[n0], b1b = sB1[n0 + 1];
                float w2a = sW2[n0], w2b = sW2[n0 + 1];
                #pragma unroll
                for (int half = 0; half < 2; ++half) {
                    float h0 = c[mt][nt][half * 2] + b1a;     h0 = h0 > 0.f ? h0 : 0.01f * h0;
                    float h1 = c[mt][nt][half * 2 + 1] + b1b; h1 = h1 > 0.f ? h1 : 0.01f * h1;
                    part[mt][half] += h0 * w2a + h1 * w2b;
                }
            }
        #pragma unroll
        for (int mt = 0; mt < 2; ++mt)
            #pragma unroll
            for (int half = 0; half < 2; ++half) {
                part[mt][half] += __shfl_xor_sync(0xFFFFFFFFu, part[mt][half], 1);
                part[mt][half] += __shfl_xor_sync(0xFFFFFFFFu, part[mt][half], 2);
            }
        if (nwid && (lane & 3) == 0) {
            #pragma unroll
            for (int mt = 0; mt < 2; ++mt)
                #pragma unroll
                for (int half = 0; half < 2; ++half) {
                    int m = warp_m + mt * 16 + half * 8 + (lane >> 2);
                    sRed[(nwid - 1) * 128 + m] = part[mt][half];
                }
        }
        __syncthreads();
        if (nwid == 0 && (lane & 3) == 0) {
            #pragma unroll
            for (int mt = 0; mt < 2; ++mt)
                #pragma unroll
                for (int half = 0; half < 2; ++half) {
                    int m = warp_m + mt * 16 + half * 8 + (lane >> 2);
                    int e = tile * 128 + m;
                    if (e < E) {
                        float weight = part[mt][half] + sRed[m] + sRed[128 + m] + sRed[256 + m]
                                     + b2v + g_ws[src[e]] + g_wd[dst[e]];
                        float u = noise[e];
                        float eps = fmaf(2e-4f - 1.f, u, 1.f - 1e-4f);
                        float gate = (logf(eps) - log1pf(-eps) + weight) * 2.f;
                        float a = 1.f / (1.f + expf(-gate));
                        aug[e] = a;
                        localSum += a;
                    }
                }
        }
        __syncthreads();

        tile = nxt;
        have = haveN;
        b ^= 1;
    }

    #pragma unroll
    for (int o = 16; o > 0; o >>= 1)
        localSum += __shfl_xor_sync(0xFFFFFFFFu, localSum, o);
    __shared__ float sPart[16];
    if (lane == 0) sPart[wid] = localSum;
    __syncthreads();
    if (tid == 0) {
        float s = 0.f;
        #pragma unroll
        for (int i = 0; i < 16; i++) s += sPart[i];
        atomicAdd(&g_sum, s);
    }
}

// ======================= host =======================
extern "C" void kernel_launch(void* const* d_in, const int* in_sizes, int n_in,
                              void* d_out, int out_size)
{
    const float* node_emb = (const float*)d_in[0];
    const float* edge_fea = (const float*)d_in[1];
    const float* noise    = (const float*)d_in[2];

    const int* src; const int* dst; int base;
    if (in_sizes[3] == in_sizes[2]) { src = (const int*)d_in[3];  dst = (const int*)d_in[4];  base = 5; }
    else                            { src = (const int*)d_in[15]; dst = (const int*)d_in[16]; base = 3; }

    const float* w_src1 = (const float*)d_in[base + 0];
    const float* b_src1 = (const float*)d_in[base + 1];
    const float* w_src2 = (const float*)d_in[base + 2];
    const float* b_src2 = (const float*)d_in[base + 3];
    const float* w_dst1 = (const float*)d_in[base + 4];
    const float* b_dst1 = (const float*)d_in[base + 5];
    const float* w_dst2 = (const float*)d_in[base + 6];
    const float* b_dst2 = (const float*)d_in[base + 7];
    const float* w_edge1 = (const float*)d_in[base + 8];
    const float* b_edge1 = (const float*)d_in[base + 9];
    const float* w_edge2 = (const float*)d_in[base + 10];
    const float* b_edge2 = (const float*)d_in[base + 11];

    const int Hd = in_sizes[base + 1];            // 128
    const int D  = in_sizes[base + 0] / Hd;       // 256
    const int N  = in_sizes[0] / D;               // 50000
    const int E  = in_sizes[2];                   // 1600000
    (void)n_in;

    float* out = (float*)d_out;
    float* aug = (out_size > E) ? (out + 1) : out;

    cudaFuncSetAttribute(node_tc, cudaFuncAttributeMaxDynamicSharedMemorySize, NODE_SMEM);
    cudaFuncSetAttribute(edge_tc, cudaFuncAttributeMaxDynamicSharedMemorySize, EDGE_SMEM);

    zero_kernel<<<1, 1>>>();

    int nTiles = (N + 127) / 128;
    dim3 ngrid(nTiles < 148 ? nTiles : 148, 2);
    node_tc<<<ngrid, 512, NODE_SMEM>>>(node_emb, N,
        w_src1, b_src1, w_src2, b_src2,
        w_dst1, b_dst1, w_dst2, b_dst2);

    int eTiles = (E + 127) / 128;
    int egrid = eTiles < 148 ? eTiles : 148;
    edge_tc<<<egrid, 512, EDGE_SMEM>>>(edge_fea, E,
        w_edge1, b_edge1, w_edge2, b_edge2,
        noise, src, dst, aug);

    if (out_size > E)
        finalize_kernel<<<1, 1>>>(out, 1.f / (float)E);
}

// round 6
// speedup vs baseline: 2.6604x; 1.4187x over previous
#include <cuda_runtime.h>
#include <cuda_bf16.h>
#include <cuda_fp16.h>
#include <stdint.h>
#include <math.h>

#define NMAX 50048

__device__ float g_ws[NMAX];
__device__ float g_wd[NMAX];
__device__ float g_sum;

__global__ void zero_kernel() { g_sum = 0.f; }
__global__ void finalize_kernel(float* out0, float invE) { *out0 = 1.f - g_sum * invE; }

__device__ __forceinline__ uint32_t smem_u32(const void* p) {
    uint32_t a;
    asm("{ .reg .u64 t; cvta.to.shared.u64 t, %1; cvt.u32.u64 %0, t; }" : "=r"(a) : "l"(p));
    return a;
}

__device__ __forceinline__ void ldsm4(uint32_t* r, uint32_t addr) {
    asm volatile("ldmatrix.sync.aligned.m8n8.x4.shared.b16 {%0,%1,%2,%3}, [%4];"
        : "=r"(r[0]), "=r"(r[1]), "=r"(r[2]), "=r"(r[3]) : "r"(addr));
}

__device__ __forceinline__ void mma_f16(float* c, const uint32_t* a, uint32_t b0, uint32_t b1) {
    asm volatile(
        "mma.sync.aligned.m16n8k16.row.col.f32.f16.f16.f32 "
        "{%0,%1,%2,%3}, {%4,%5,%6,%7}, {%8,%9}, {%0,%1,%2,%3};\n"
        : "+f"(c[0]), "+f"(c[1]), "+f"(c[2]), "+f"(c[3])
        : "r"(a[0]), "r"(a[1]), "r"(a[2]), "r"(a[3]), "r"(b0), "r"(b1));
}

// -------- edge k-step: single-pass fp16 --------
__device__ __forceinline__ void k_step_e1(float (&c)[2][4][4],
    uint32_t aHi, uint32_t bHi, int bNpStride)
{
    uint32_t ah[2][4], bh[2][4];
    ldsm4(ah[0], aHi);  ldsm4(ah[1], aHi + 4352);
    ldsm4(bh[0], bHi);  ldsm4(bh[1], bHi + bNpStride);
    #pragma unroll
    for (int mt = 0; mt < 2; ++mt)
        #pragma unroll
        for (int np = 0; np < 2; ++np)
            #pragma unroll
            for (int s = 0; s < 2; ++s)
                mma_f16(c[mt][np * 2 + s], ah[mt], bh[np][2 * s], bh[np][2 * s + 1]);
}

// -------- node k-step: fp16 2-pass (Ah·Bh + Ah·Bl), B split exact --------
__device__ __forceinline__ void k_step_n2(float (&c)[2][4][4],
    uint32_t aHi, uint32_t bHi, uint32_t bLo, int bNpStride)
{
    uint32_t ah[2][4], bh[2][4], bl[2][4];
    ldsm4(ah[0], aHi);  ldsm4(ah[1], aHi + 4352);
    ldsm4(bh[0], bHi);  ldsm4(bh[1], bHi + bNpStride);
    ldsm4(bl[0], bLo);  ldsm4(bl[1], bLo + bNpStride);
    #pragma unroll
    for (int mt = 0; mt < 2; ++mt)
        #pragma unroll
        for (int np = 0; np < 2; ++np)
            #pragma unroll
            for (int s = 0; s < 2; ++s)
                mma_f16(c[mt][np * 2 + s], ah[mt], bh[np][2 * s], bh[np][2 * s + 1]);
    #pragma unroll
    for (int mt = 0; mt < 2; ++mt)
        #pragma unroll
        for (int np = 0; np < 2; ++np)
            #pragma unroll
            for (int s = 0; s < 2; ++s)
                mma_f16(c[mt][np * 2 + s], ah[mt], bl[np][2 * s], bl[np][2 * s + 1]);
}

// ---------------- smem layouts ----------------
#define E_BT  0
#define E_A   34816
#define E_B1  104448
#define E_W2  104960
#define E_RED 105472
#define EDGE_SMEM 108544

#define N_BTH 0
#define N_BTL 67584
#define N_A   135168
#define N_B1  169984
#define N_W2  170496
#define N_RED 171008
#define NODE_SMEM 172544

// ======================= NODE MLPs (fp16 2-pass) =======================
__global__ void __launch_bounds__(512, 1)
node_tc(const float* __restrict__ X, int N,
        const float* __restrict__ Ws1, const float* __restrict__ bs1,
        const float* __restrict__ ws2, const float* __restrict__ bs2,
        const float* __restrict__ Wd1, const float* __restrict__ bd1,
        const float* __restrict__ wd2, const float* __restrict__ bd2)
{
    extern __shared__ char smem[];
    const uint32_t sb = smem_u32(smem);
    const int tid = threadIdx.x;
    const int wid = tid >> 5, lane = tid & 31;
    const int warp_m = (wid >> 2) * 32, warp_n = (wid & 3) * 32;
    const int nwid = wid & 3;

    const float* W1  = blockIdx.y ? Wd1 : Ws1;
    const float* b1g = blockIdx.y ? bd1 : bs1;
    const float* w2g = blockIdx.y ? wd2 : ws2;
    const float* b2g = blockIdx.y ? bd2 : bs2;
    float* outp = blockIdx.y ? g_wd : g_ws;

    float* sB1 = (float*)(smem + N_B1);
    float* sW2 = (float*)(smem + N_W2);
    float* sRed = (float*)(smem + N_RED);

    // Bt[n][k] fp16 hi/lo, stride 528. W1 is [K=256][N=128].
    for (int idx = tid; idx < 256 * 128; idx += 512) {
        int n = idx & 127, k = idx >> 7;
        float w = W1[idx];
        __half h = __float2half_rn(w);
        float r = w - __half2float(h);
        int byte = n * 528 + k * 2;
        *(__half*)(smem + N_BTH + byte) = h;
        *(__half*)(smem + N_BTL + byte) = __float2half_rn(r);
    }
    if (tid < 128) { sB1[tid] = b1g[tid]; sW2[tid] = w2g[tid]; }
    const float b2v = b2g[0];
    __syncthreads();

    const uint32_t aLaneOff = (uint32_t)((warp_m + (lane & 15)) * 272 + (lane >> 4) * 16);
    const uint32_t bLaneRow = (uint32_t)(warp_n + (lane & 7) + ((lane >> 4) << 3));
    const uint32_t bLaneOff = bLaneRow * 528 + (((uint32_t)lane >> 3) & 1) * 16;

    const int numTiles = (N + 127) >> 7;
    for (int tile = blockIdx.x; tile < numTiles; tile += gridDim.x) {
        float c[2][4][4];
        #pragma unroll
        for (int i = 0; i < 2; i++)
            #pragma unroll
            for (int j = 0; j < 4; j++)
                #pragma unroll
                for (int q = 0; q < 4; q++) c[i][j][q] = 0.f;

        int row = tile * 128 + (tid >> 2);
        if (row >= N) row = N - 1;
        const float4* xp = (const float4*)(X + (size_t)row * 256);
        const int q = tid & 3;
        const int myrow = tid >> 2;

        for (int kc = 0; kc < 2; ++kc) {
            __syncthreads();
            #pragma unroll
            for (int i = 0; i < 8; ++i) {
                float4 v = xp[kc * 32 + q * 8 + i];
                __half2 h0 = __floats2half2_rn(v.x, v.y);
                __half2 h1 = __floats2half2_rn(v.z, v.w);
                int byte = myrow * 272 + (q * 32 + i * 4) * 2;
                *(uint2*)(smem + N_A + byte) = make_uint2(*(uint32_t*)&h0, *(uint32_t*)&h1);
            }
            __syncthreads();
            const uint32_t aHi = sb + N_A + aLaneOff;
            const uint32_t bHi = sb + N_BTH + bLaneOff + kc * 256;
            const uint32_t bLo = sb + N_BTL + bLaneOff + kc * 256;
            #pragma unroll
            for (int kt = 0; kt < 8; ++kt)
                k_step_n2(c, aHi + kt * 32, bHi + kt * 32, bLo + kt * 32, 16 * 528);
        }

        float part[2][2] = {{0.f, 0.f}, {0.f, 0.f}};
        #pragma unroll
        for (int mt = 0; mt < 2; ++mt)
            #pragma unroll
            for (int nt = 0; nt < 4; ++nt) {
                int n0 = warp_n + nt * 8 + (lane & 3) * 2;
                float b1a = sB1[n0], b1b = sB1[n0 + 1];
                float w2a = sW2[n0], w2b = sW2[n0 + 1];
                #pragma unroll
                for (int half = 0; half < 2; ++half) {
                    float h0 = c[mt][nt][half * 2] + b1a;     h0 = h0 > 0.f ? h0 : 0.01f * h0;
                    float h1 = c[mt][nt][half * 2 + 1] + b1b; h1 = h1 > 0.f ? h1 : 0.01f * h1;
                    part[mt][half] += h0 * w2a + h1 * w2b;
                }
            }
        #pragma unroll
        for (int mt = 0; mt < 2; ++mt)
            #pragma unroll
            for (int half = 0; half < 2; ++half) {
                part[mt][half] += __shfl_xor_sync(0xFFFFFFFFu, part[mt][half], 1);
                part[mt][half] += __shfl_xor_sync(0xFFFFFFFFu, part[mt][half], 2);
            }
        if (nwid && (lane & 3) == 0) {
            #pragma unroll
            for (int mt = 0; mt < 2; ++mt)
                #pragma unroll
                for (int half = 0; half < 2; ++half) {
                    int m = warp_m + mt * 16 + half * 8 + (lane >> 2);
                    sRed[(nwid - 1) * 128 + m] = part[mt][half];
                }
        }
        __syncthreads();
        if (nwid == 0 && (lane & 3) == 0) {
            #pragma unroll
            for (int mt = 0; mt < 2; ++mt)
                #pragma unroll
                for (int half = 0; half < 2; ++half) {
                    int m = warp_m + mt * 16 + half * 8 + (lane >> 2);
                    int nidx = tile * 128 + m;
                    if (nidx < N)
                        outp[nidx] = part[mt][half] + sRed[m] + sRed[128 + m] + sRed[256 + m] + b2v;
                }
        }
        __syncthreads();
    }
}

// ======================= EDGE MLP (fp16 single-pass, fused) =======================
__global__ void __launch_bounds__(512, 1)
edge_tc(const float* __restrict__ X, int E,
        const float* __restrict__ W1, const float* __restrict__ b1g,
        const float* __restrict__ w2g, const float* __restrict__ b2g,
        const float* __restrict__ noise, const int* __restrict__ src,
        const int* __restrict__ dst, float* __restrict__ aug)
{
    extern __shared__ char smem[];
    const uint32_t sb = smem_u32(smem);
    const int tid = threadIdx.x;
    const int wid = tid >> 5, lane = tid & 31;
    const int warp_m = (wid >> 2) * 32, warp_n = (wid & 3) * 32;
    const int nwid = wid & 3;
    const bool owner = (nwid == 0) && ((lane & 3) == 0);

    float* sB1 = (float*)(smem + E_B1);
    float* sW2 = (float*)(smem + E_W2);
    float* sRed = (float*)(smem + E_RED);

    // Bt[n][k] fp16 (hi only), stride 272. W1 is [K=128][N=128].
    for (int idx = tid; idx < 128 * 128; idx += 512) {
        int n = idx & 127, k = idx >> 7;
        *(__half*)(smem + E_BT + n * 272 + k * 2) = __float2half_rn(W1[idx]);
    }
    if (tid < 128) { sB1[tid] = b1g[tid]; sW2[tid] = w2g[tid]; }
    const float b2v = b2g[0];
    __syncthreads();

    const uint32_t aLaneOff = (uint32_t)((warp_m + (lane & 15)) * 272 + (lane >> 4) * 16);
    const uint32_t bLaneRow = (uint32_t)(warp_n + (lane & 7) + ((lane >> 4) << 3));
    const uint32_t bLaneOff = bLaneRow * 272 + (((uint32_t)lane >> 3) & 1) * 16;
    const uint32_t bHi = sb + E_BT + bLaneOff;

    const int numTiles = (E + 127) >> 7;
    float localSum = 0.f;

    const int q = tid & 3;
    const int myrow = tid >> 2;

    float4 st[8];
    int tile = blockIdx.x;
    bool have = tile < numTiles;
    if (have) {
        int row = tile * 128 + myrow;
        if (row >= E) row = E - 1;
        const float4* xp = (const float4*)(X + (size_t)row * 128);
        #pragma unroll
        for (int i = 0; i < 8; ++i) st[i] = xp[q * 8 + i];
    }

    int b = 0;
    while (have) {
        // prefetch epilogue operands for THIS tile (hidden under MMA)
        int   eIdx[4];
        float gw[4], nz[4];
        if (owner) {
            #pragma unroll
            for (int j = 0; j < 4; ++j) {
                int m = warp_m + (j >> 1) * 16 + (j & 1) * 8 + (lane >> 2);
                int e = tile * 128 + m;
                if (e < E) {
                    eIdx[j] = e;
                    int s = __ldg(&src[e]), d = __ldg(&dst[e]);
                    nz[j] = __ldg(&noise[e]);
                    gw[j] = g_ws[s] + g_wd[d];
                } else { eIdx[j] = -1; gw[j] = 0.f; nz[j] = 0.5f; }
            }
        }

        // convert stash (fp16) into A buffer b
        {
            char* AH = smem + E_A + b * 34816;
            #pragma unroll
            for (int i = 0; i < 8; ++i) {
                __half2 h0 = __floats2half2_rn(st[i].x, st[i].y);
                __half2 h1 = __floats2half2_rn(st[i].z, st[i].w);
                int byte = myrow * 272 + (q * 32 + i * 4) * 2;
                *(uint2*)(AH + byte) = make_uint2(*(uint32_t*)&h0, *(uint32_t*)&h1);
            }
        }
        __syncthreads();   // sync1: A buf b ready

        // prefetch next X tile (LDG in flight during MMA)
        int nxt = tile + gridDim.x;
        bool haveN = nxt < numTiles;
        if (haveN) {
            int row = nxt * 128 + myrow;
            if (row >= E) row = E - 1;
            const float4* xp = (const float4*)(X + (size_t)row * 128);
            #pragma unroll
            for (int i = 0; i < 8; ++i) st[i] = xp[q * 8 + i];
        }

        float c[2][4][4];
        #pragma unroll
        for (int i = 0; i < 2; i++)
            #pragma unroll
            for (int j = 0; j < 4; j++)
                #pragma unroll
                for (int qq = 0; qq < 4; qq++) c[i][j][qq] = 0.f;

        const uint32_t aHi = sb + E_A + b * 34816 + aLaneOff;
        #pragma unroll
        for (int kt = 0; kt < 8; ++kt)
            k_step_e1(c, aHi + kt * 32, bHi + kt * 32, 16 * 272);

        // epilogue
        float part[2][2] = {{0.f, 0.f}, {0.f, 0.f}};
        #pragma unroll
        for (int mt = 0; mt < 2; ++mt)
            #pragma unroll
            for (int nt = 0; nt < 4; ++nt) {
                int n0 = warp_n + nt * 8 + (lane & 3) * 2;
                float b1a = sB1[n0], b1b = sB1[n0 + 1];
                float w2a = sW2[n0], w2b = sW2[n0 + 1];
                #pragma unroll
                for (int half = 0; half < 2; ++half) {
                    float h0 = c[mt][nt][half * 2] + b1a;     h0 = h0 > 0.f ? h0 : 0.01f * h0;
                    float h1 = c[mt][nt][half * 2 + 1] + b1b; h1 = h1 > 0.f ? h1 : 0.01f * h1;
                    part[mt][half] += h0 * w2a + h1 * w2b;
                }
            }
        #pragma unroll
        for (int mt = 0; mt < 2; ++mt)
            #pragma unroll
            for (int half = 0; half < 2; ++half) {
                part[mt][half] += __shfl_xor_sync(0xFFFFFFFFu, part[mt][half], 1);
                part[mt][half] += __shfl_xor_sync(0xFFFFFFFFu, part[mt][half], 2);
            }

        float* sRedB = sRed + (b ? 384 : 0);
        if (nwid && (lane & 3) == 0) {
            #pragma unroll
            for (int mt = 0; mt < 2; ++mt)
                #pragma unroll
                for (int half = 0; half < 2; ++half) {
                    int m = warp_m + mt * 16 + half * 8 + (lane >> 2);
                    sRedB[(nwid - 1) * 128 + m] = part[mt][half];
                }
        }
        __syncthreads();   // sync2: sRed buf b ready
        if (owner) {
            #pragma unroll
            for (int j = 0; j < 4; ++j) {
                int mt = j >> 1, half = j & 1;
                int m = warp_m + mt * 16 + half * 8 + (lane >> 2);
                if (eIdx[j] >= 0) {
                    float weight = part[mt][half] + sRedB[m] + sRedB[128 + m] + sRedB[256 + m]
                                 + b2v + gw[j];
                    float u = nz[j];
                    float eps = fmaf(2e-4f - 1.f, u, 1.f - 1e-4f);
                    float gate = (logf(eps) - log1pf(-eps) + weight) * 2.f;
                    float a = 1.f / (1.f + expf(-gate));
                    aug[eIdx[j]] = a;
                    localSum += a;
                }
            }
        }

        tile = nxt;
        have = haveN;
        b ^= 1;
    }

    #pragma unroll
    for (int o = 16; o > 0; o >>= 1)
        localSum += __shfl_xor_sync(0xFFFFFFFFu, localSum, o);
    __shared__ float sPart[16];
    if (lane == 0) sPart[wid] = localSum;
    __syncthreads();
    if (tid == 0) {
        float s = 0.f;
        #pragma unroll
        for (int i = 0; i < 16; i++) s += sPart[i];
        atomicAdd(&g_sum, s);
    }
}

// ======================= host =======================
extern "C" void kernel_launch(void* const* d_in, const int* in_sizes, int n_in,
                              void* d_out, int out_size)
{
    const float* node_emb = (const float*)d_in[0];
    const float* edge_fea = (const float*)d_in[1];
    const float* noise    = (const float*)d_in[2];

    const int* src; const int* dst; int base;
    if (in_sizes[3] == in_sizes[2]) { src = (const int*)d_in[3];  dst = (const int*)d_in[4];  base = 5; }
    else                            { src = (const int*)d_in[15]; dst = (const int*)d_in[16]; base = 3; }

    const float* w_src1 = (const float*)d_in[base + 0];
    const float* b_src1 = (const float*)d_in[base + 1];
    const float* w_src2 = (const float*)d_in[base + 2];
    const float* b_src2 = (const float*)d_in[base + 3];
    const float* w_dst1 = (const float*)d_in[base + 4];
    const float* b_dst1 = (const float*)d_in[base + 5];
    const float* w_dst2 = (const float*)d_in[base + 6];
    const float* b_dst2 = (const float*)d_in[base + 7];
    const float* w_edge1 = (const float*)d_in[base + 8];
    const float* b_edge1 = (const float*)d_in[base + 9];
    const float* w_edge2 = (const float*)d_in[base + 10];
    const float* b_edge2 = (const float*)d_in[base + 11];

    const int Hd = in_sizes[base + 1];            // 128
    const int D  = in_sizes[base + 0] / Hd;       // 256
    const int N  = in_sizes[0] / D;               // 50000
    const int E  = in_sizes[2];                   // 1600000
    (void)n_in;

    float* out = (float*)d_out;
    float* aug = (out_size > E) ? (out + 1) : out;

    cudaFuncSetAttribute(node_tc, cudaFuncAttributeMaxDynamicSharedMemorySize, NODE_SMEM);
    cudaFuncSetAttribute(edge_tc, cudaFuncAttributeMaxDynamicSharedMemorySize, EDGE_SMEM);

    zero_kernel<<<1, 1>>>();

    int nTiles = (N + 127) / 128;
    dim3 ngrid(nTiles < 148 ? nTiles : 148, 2);
    node_tc<<<ngrid, 512, NODE_SMEM>>>(node_emb, N,
        w_src1, b_src1, w_src2, b_src2,
        w_dst1, b_dst1, w_dst2, b_dst2);

    int eTiles = (E + 127) / 128;
    int egrid = eTiles < 148 ? eTiles : 148;
    edge_tc<<<egrid, 512, EDGE_SMEM>>>(edge_fea, E,
        w_edge1, b_edge1, w_edge2, b_edge2,
        noise, src, dst, aug);

    if (out_size > E)
        finalize_kernel<<<1, 1>>>(out, 1.f / (float)E);
}

// round 7
// speedup vs baseline: 2.7927x; 1.0497x over previous
#include <cuda_runtime.h>
#include <cuda_bf16.h>
#include <cuda_fp16.h>
#include <stdint.h>
#include <math.h>

#define NMAX 50048

__device__ float g_ws[NMAX];
__device__ float g_wd[NMAX];
__device__ float g_sum;

__global__ void zero_kernel() { g_sum = 0.f; }
__global__ void finalize_kernel(float* out0, float invE) { *out0 = 1.f - g_sum * invE; }

__device__ __forceinline__ uint32_t smem_u32(const void* p) {
    uint32_t a;
    asm("{ .reg .u64 t; cvta.to.shared.u64 t, %1; cvt.u32.u64 %0, t; }" : "=r"(a) : "l"(p));
    return a;
}

__device__ __forceinline__ void ldsm4(uint32_t* r, uint32_t addr) {
    asm volatile("ldmatrix.sync.aligned.m8n8.x4.shared.b16 {%0,%1,%2,%3}, [%4];"
        : "=r"(r[0]), "=r"(r[1]), "=r"(r[2]), "=r"(r[3]) : "r"(addr));
}

__device__ __forceinline__ void mma_f16(float* c, const uint32_t* a, uint32_t b0, uint32_t b1) {
    asm volatile(
        "mma.sync.aligned.m16n8k16.row.col.f32.f16.f16.f32 "
        "{%0,%1,%2,%3}, {%4,%5,%6,%7}, {%8,%9}, {%0,%1,%2,%3};\n"
        : "+f"(c[0]), "+f"(c[1]), "+f"(c[2]), "+f"(c[3])
        : "r"(a[0]), "r"(a[1]), "r"(a[2]), "r"(a[3]), "r"(b0), "r"(b1));
}

// -------- edge k-step: single-pass fp16 --------
__device__ __forceinline__ void k_step_e1(float (&c)[2][4][4],
    uint32_t aHi, uint32_t bHi, int bNpStride)
{
    uint32_t ah[2][4], bh[2][4];
    ldsm4(ah[0], aHi);  ldsm4(ah[1], aHi + 4352);
    ldsm4(bh[0], bHi);  ldsm4(bh[1], bHi + bNpStride);
    #pragma unroll
    for (int mt = 0; mt < 2; ++mt)
        #pragma unroll
        for (int np = 0; np < 2; ++np)
            #pragma unroll
            for (int s = 0; s < 2; ++s)
                mma_f16(c[mt][np * 2 + s], ah[mt], bh[np][2 * s], bh[np][2 * s + 1]);
}

// -------- node k-step: fp16 2-pass (Ah·Bh + Ah·Bl), B split exact --------
__device__ __forceinline__ void k_step_n2(float (&c)[2][4][4],
    uint32_t aHi, uint32_t bHi, uint32_t bLo, int bNpStride)
{
    uint32_t ah[2][4], bh[2][4], bl[2][4];
    ldsm4(ah[0], aHi);  ldsm4(ah[1], aHi + 4352);
    ldsm4(bh[0], bHi);  ldsm4(bh[1], bHi + bNpStride);
    ldsm4(bl[0], bLo);  ldsm4(bl[1], bLo + bNpStride);
    #pragma unroll
    for (int mt = 0; mt < 2; ++mt)
        #pragma unroll
        for (int np = 0; np < 2; ++np)
            #pragma unroll
            for (int s = 0; s < 2; ++s)
                mma_f16(c[mt][np * 2 + s], ah[mt], bh[np][2 * s], bh[np][2 * s + 1]);
    #pragma unroll
    for (int mt = 0; mt < 2; ++mt)
        #pragma unroll
        for (int np = 0; np < 2; ++np)
            #pragma unroll
            for (int s = 0; s < 2; ++s)
                mma_f16(c[mt][np * 2 + s], ah[mt], bl[np][2 * s], bl[np][2 * s + 1]);
}

// ---------------- smem layouts ----------------
// Edge (256 thr, M=64, 2 CTAs/SM): BT 34816 | A 2x17408 | B1 512 | W2 512 | RED 2x1024
#define E_BT  0
#define E_A   34816
#define E_B1  69632
#define E_W2  70144
#define E_RED 70656
#define EDGE_SMEM 72704

#define N_BTH 0
#define N_BTL 67584
#define N_A   135168
#define N_B1  169984
#define N_W2  170496
#define N_RED 171008
#define NODE_SMEM 172544

// ======================= NODE MLPs (fp16 2-pass, unchanged) =======================
__global__ void __launch_bounds__(512, 1)
node_tc(const float* __restrict__ X, int N,
        const float* __restrict__ Ws1, const float* __restrict__ bs1,
        const float* __restrict__ ws2, const float* __restrict__ bs2,
        const float* __restrict__ Wd1, const float* __restrict__ bd1,
        const float* __restrict__ wd2, const float* __restrict__ bd2)
{
    extern __shared__ char smem[];
    const uint32_t sb = smem_u32(smem);
    const int tid = threadIdx.x;
    const int wid = tid >> 5, lane = tid & 31;
    const int warp_m = (wid >> 2) * 32, warp_n = (wid & 3) * 32;
    const int nwid = wid & 3;

    const float* W1  = blockIdx.y ? Wd1 : Ws1;
    const float* b1g = blockIdx.y ? bd1 : bs1;
    const float* w2g = blockIdx.y ? wd2 : ws2;
    const float* b2g = blockIdx.y ? bd2 : bs2;
    float* outp = blockIdx.y ? g_wd : g_ws;

    float* sB1 = (float*)(smem + N_B1);
    float* sW2 = (float*)(smem + N_W2);
    float* sRed = (float*)(smem + N_RED);

    for (int idx = tid; idx < 256 * 128; idx += 512) {
        int n = idx & 127, k = idx >> 7;
        float w = W1[idx];
        __half h = __float2half_rn(w);
        float r = w - __half2float(h);
        int byte = n * 528 + k * 2;
        *(__half*)(smem + N_BTH + byte) = h;
        *(__half*)(smem + N_BTL + byte) = __float2half_rn(r);
    }
    if (tid < 128) { sB1[tid] = b1g[tid]; sW2[tid] = w2g[tid]; }
    const float b2v = b2g[0];
    __syncthreads();

    const uint32_t aLaneOff = (uint32_t)((warp_m + (lane & 15)) * 272 + (lane >> 4) * 16);
    const uint32_t bLaneRow = (uint32_t)(warp_n + (lane & 7) + ((lane >> 4) << 3));
    const uint32_t bLaneOff = bLaneRow * 528 + (((uint32_t)lane >> 3) & 1) * 16;

    const int numTiles = (N + 127) >> 7;
    for (int tile = blockIdx.x; tile < numTiles; tile += gridDim.x) {
        float c[2][4][4];
        #pragma unroll
        for (int i = 0; i < 2; i++)
            #pragma unroll
            for (int j = 0; j < 4; j++)
                #pragma unroll
                for (int q = 0; q < 4; q++) c[i][j][q] = 0.f;

        int row = tile * 128 + (tid >> 2);
        if (row >= N) row = N - 1;
        const float4* xp = (const float4*)(X + (size_t)row * 256);
        const int q = tid & 3;
        const int myrow = tid >> 2;

        for (int kc = 0; kc < 2; ++kc) {
            __syncthreads();
            #pragma unroll
            for (int i = 0; i < 8; ++i) {
                float4 v = xp[kc * 32 + q * 8 + i];
                __half2 h0 = __floats2half2_rn(v.x, v.y);
                __half2 h1 = __floats2half2_rn(v.z, v.w);
                int byte = myrow * 272 + (q * 32 + i * 4) * 2;
                *(uint2*)(smem + N_A + byte) = make_uint2(*(uint32_t*)&h0, *(uint32_t*)&h1);
            }
            __syncthreads();
            const uint32_t aHi = sb + N_A + aLaneOff;
            const uint32_t bHi = sb + N_BTH + bLaneOff + kc * 256;
            const uint32_t bLo = sb + N_BTL + bLaneOff + kc * 256;
            #pragma unroll
            for (int kt = 0; kt < 8; ++kt)
                k_step_n2(c, aHi + kt * 32, bHi + kt * 32, bLo + kt * 32, 16 * 528);
        }

        float part[2][2] = {{0.f, 0.f}, {0.f, 0.f}};
        #pragma unroll
        for (int mt = 0; mt < 2; ++mt)
            #pragma unroll
            for (int nt = 0; nt < 4; ++nt) {
                int n0 = warp_n + nt * 8 + (lane & 3) * 2;
                float b1a = sB1[n0], b1b = sB1[n0 + 1];
                float w2a = sW2[n0], w2b = sW2[n0 + 1];
                #pragma unroll
                for (int half = 0; half < 2; ++half) {
                    float h0 = c[mt][nt][half * 2] + b1a;     h0 = h0 > 0.f ? h0 : 0.01f * h0;
                    float h1 = c[mt][nt][half * 2 + 1] + b1b; h1 = h1 > 0.f ? h1 : 0.01f * h1;
                    part[mt][half] += h0 * w2a + h1 * w2b;
                }
            }
        #pragma unroll
        for (int mt = 0; mt < 2; ++mt)
            #pragma unroll
            for (int half = 0; half < 2; ++half) {
                part[mt][half] += __shfl_xor_sync(0xFFFFFFFFu, part[mt][half], 1);
                part[mt][half] += __shfl_xor_sync(0xFFFFFFFFu, part[mt][half], 2);
            }
        if (nwid && (lane & 3) == 0) {
            #pragma unroll
            for (int mt = 0; mt < 2; ++mt)
                #pragma unroll
                for (int half = 0; half < 2; ++half) {
                    int m = warp_m + mt * 16 + half * 8 + (lane >> 2);
                    sRed[(nwid - 1) * 128 + m] = part[mt][half];
                }
        }
        __syncthreads();
        if (nwid == 0 && (lane & 3) == 0) {
            #pragma unroll
            for (int mt = 0; mt < 2; ++mt)
                #pragma unroll
                for (int half = 0; half < 2; ++half) {
                    int m = warp_m + mt * 16 + half * 8 + (lane >> 2);
                    int nidx = tile * 128 + m;
                    if (nidx < N)
                        outp[nidx] = part[mt][half] + sRed[m] + sRed[128 + m] + sRed[256 + m] + b2v;
                }
        }
        __syncthreads();
    }
}

// ======================= EDGE MLP (fp16 single-pass, M=64, 2 CTAs/SM) =======================
__global__ void __launch_bounds__(256, 2)
edge_tc(const float* __restrict__ X, int E,
        const float* __restrict__ W1, const float* __restrict__ b1g,
        const float* __restrict__ w2g, const float* __restrict__ b2g,
        const float* __restrict__ noise, const int* __restrict__ src,
        const int* __restrict__ dst, float* __restrict__ aug)
{
    extern __shared__ char smem[];
    const uint32_t sb = smem_u32(smem);
    const int tid = threadIdx.x;
    const int wid = tid >> 5, lane = tid & 31;
    const int warp_m = (wid >> 2) * 32, warp_n = (wid & 3) * 32;
    const int nwid = wid & 3;
    const bool owner = (nwid == 0) && ((lane & 3) == 0);

    float* sB1 = (float*)(smem + E_B1);
    float* sW2 = (float*)(smem + E_W2);
    float* sRed = (float*)(smem + E_RED);

    // Bt[n][k] fp16 (hi only), stride 272. W1 is [K=128][N=128].
    for (int idx = tid; idx < 128 * 128; idx += 256) {
        int n = idx & 127, k = idx >> 7;
        *(__half*)(smem + E_BT + n * 272 + k * 2) = __float2half_rn(W1[idx]);
    }
    if (tid < 128) { sB1[tid] = b1g[tid]; sW2[tid] = w2g[tid]; }
    const float b2v = b2g[0];
    __syncthreads();

    const uint32_t aLaneOff = (uint32_t)((warp_m + (lane & 15)) * 272 + (lane >> 4) * 16);
    const uint32_t bLaneRow = (uint32_t)(warp_n + (lane & 7) + ((lane >> 4) << 3));
    const uint32_t bLaneOff = bLaneRow * 272 + (((uint32_t)lane >> 3) & 1) * 16;
    const uint32_t bHi = sb + E_BT + bLaneOff;

    const int numTiles = (E + 63) >> 6;   // M=64 tiles
    float localSum = 0.f;

    const int q = tid & 3;
    const int myrow = tid >> 2;           // 0..63

    float4 st[8];
    int tile = blockIdx.x;
    bool have = tile < numTiles;
    if (have) {
        int row = tile * 64 + myrow;
        if (row >= E) row = E - 1;
        const float4* xp = (const float4*)(X + (size_t)row * 128);
        #pragma unroll
        for (int i = 0; i < 8; ++i) st[i] = xp[q * 8 + i];
    }

    int b = 0;
    while (have) {
        // prefetch epilogue operands for THIS tile (hidden under MMA)
        int   eIdx[4];
        float gw[4], nz[4];
        if (owner) {
            #pragma unroll
            for (int j = 0; j < 4; ++j) {
                int m = warp_m + (j >> 1) * 16 + (j & 1) * 8 + (lane >> 2);
                int e = tile * 64 + m;
                if (e < E) {
                    eIdx[j] = e;
                    int s = __ldg(&src[e]), d = __ldg(&dst[e]);
                    nz[j] = __ldg(&noise[e]);
                    gw[j] = g_ws[s] + g_wd[d];
                } else { eIdx[j] = -1; gw[j] = 0.f; nz[j] = 0.5f; }
            }
        }

        // convert stash (fp16) into A buffer b
        {
            char* AH = smem + E_A + b * 17408;
            #pragma unroll
            for (int i = 0; i < 8; ++i) {
                __half2 h0 = __floats2half2_rn(st[i].x, st[i].y);
                __half2 h1 = __floats2half2_rn(st[i].z, st[i].w);
                int byte = myrow * 272 + (q * 32 + i * 4) * 2;
                *(uint2*)(AH + byte) = make_uint2(*(uint32_t*)&h0, *(uint32_t*)&h1);
            }
        }
        __syncthreads();   // sync1: A buf b ready

        // prefetch next X tile (LDG in flight during MMA)
        int nxt = tile + gridDim.x;
        bool haveN = nxt < numTiles;
        if (haveN) {
            int row = nxt * 64 + myrow;
            if (row >= E) row = E - 1;
            const float4* xp = (const float4*)(X + (size_t)row * 128);
            #pragma unroll
            for (int i = 0; i < 8; ++i) st[i] = xp[q * 8 + i];
        }

        float c[2][4][4];
        #pragma unroll
        for (int i = 0; i < 2; i++)
            #pragma unroll
            for (int j = 0; j < 4; j++)
                #pragma unroll
                for (int qq = 0; qq < 4; qq++) c[i][j][qq] = 0.f;

        const uint32_t aHi = sb + E_A + b * 17408 + aLaneOff;
        #pragma unroll
        for (int kt = 0; kt < 8; ++kt)
            k_step_e1(c, aHi + kt * 32, bHi + kt * 32, 16 * 272);

        // epilogue
        float part[2][2] = {{0.f, 0.f}, {0.f, 0.f}};
        #pragma unroll
        for (int mt = 0; mt < 2; ++mt)
            #pragma unroll
            for (int nt = 0; nt < 4; ++nt) {
                int n0 = warp_n + nt * 8 + (lane & 3) * 2;
                float b1a = sB1[n0], b1b = sB1[n0 + 1];
                float w2a = sW2[n0], w2b = sW2[n0 + 1];
                #pragma unroll
                for (int half = 0; half < 2; ++half) {
                    float h0 = c[mt][nt][half * 2] + b1a;     h0 = h0 > 0.f ? h0 : 0.01f * h0;
                    float h1 = c[mt][nt][half * 2 + 1] + b1b; h1 = h1 > 0.f ? h1 : 0.01f * h1;
                    part[mt][half] += h0 * w2a + h1 * w2b;
                }
            }
        #pragma unroll
        for (int mt = 0; mt < 2; ++mt)
            #pragma unroll
            for (int half = 0; half < 2; ++half) {
                part[mt][half] += __shfl_xor_sync(0xFFFFFFFFu, part[mt][half], 1);
                part[mt][half] += __shfl_xor_sync(0xFFFFFFFFu, part[mt][half], 2);
            }

        float* sRedB = sRed + (b ? 192 : 0);
        if (nwid && (lane & 3) == 0) {
            #pragma unroll
            for (int mt = 0; mt < 2; ++mt)
                #pragma unroll
                for (int half = 0; half < 2; ++half) {
                    int m = warp_m + mt * 16 + half * 8 + (lane >> 2);
                    sRedB[(nwid - 1) * 64 + m] = part[mt][half];
                }
        }
        __syncthreads();   // sync2: sRed buf b ready
        if (owner) {
            #pragma unroll
            for (int j = 0; j < 4; ++j) {
                int mt = j >> 1, half = j & 1;
                int m = warp_m + mt * 16 + half * 8 + (lane >> 2);
                if (eIdx[j] >= 0) {
                    float weight = part[mt][half] + sRedB[m] + sRedB[64 + m] + sRedB[128 + m]
                                 + b2v + gw[j];
                    float u = nz[j];
                    float eps = fmaf(2e-4f - 1.f, u, 1.f - 1e-4f);
                    float gate = (logf(eps) - log1pf(-eps) + weight) * 2.f;
                    float a = 1.f / (1.f + expf(-gate));
                    aug[eIdx[j]] = a;
                    localSum += a;
                }
            }
        }

        tile = nxt;
        have = haveN;
        b ^= 1;
    }

    #pragma unroll
    for (int o = 16; o > 0; o >>= 1)
        localSum += __shfl_xor_sync(0xFFFFFFFFu, localSum, o);
    __shared__ float sPart[8];
    if (lane == 0) sPart[wid] = localSum;
    __syncthreads();
    if (tid == 0) {
        float s = 0.f;
        #pragma unroll
        for (int i = 0; i < 8; i++) s += sPart[i];
        atomicAdd(&g_sum, s);
    }
}

// ======================= host =======================
extern "C" void kernel_launch(void* const* d_in, const int* in_sizes, int n_in,
                              void* d_out, int out_size)
{
    const float* node_emb = (const float*)d_in[0];
    const float* edge_fea = (const float*)d_in[1];
    const float* noise    = (const float*)d_in[2];

    const int* src; const int* dst; int base;
    if (in_sizes[3] == in_sizes[2]) { src = (const int*)d_in[3];  dst = (const int*)d_in[4];  base = 5; }
    else                            { src = (const int*)d_in[15]; dst = (const int*)d_in[16]; base = 3; }

    const float* w_src1 = (const float*)d_in[base + 0];
    const float* b_src1 = (const float*)d_in[base + 1];
    const float* w_src2 = (const float*)d_in[base + 2];
    const float* b_src2 = (const float*)d_in[base + 3];
    const float* w_dst1 = (const float*)d_in[base + 4];
    const float* b_dst1 = (const float*)d_in[base + 5];
    const float* w_dst2 = (const float*)d_in[base + 6];
    const float* b_dst2 = (const float*)d_in[base + 7];
    const float* w_edge1 = (const float*)d_in[base + 8];
    const float* b_edge1 = (const float*)d_in[base + 9];
    const float* w_edge2 = (const float*)d_in[base + 10];
    const float* b_edge2 = (const float*)d_in[base + 11];

    const int Hd = in_sizes[base + 1];            // 128
    const int D  = in_sizes[base + 0] / Hd;       // 256
    const int N  = in_sizes[0] / D;               // 50000
    const int E  = in_sizes[2];                   // 1600000
    (void)n_in;

    float* out = (float*)d_out;
    float* aug = (out_size > E) ? (out + 1) : out;

    cudaFuncSetAttribute(node_tc, cudaFuncAttributeMaxDynamicSharedMemorySize, NODE_SMEM);
    cudaFuncSetAttribute(edge_tc, cudaFuncAttributeMaxDynamicSharedMemorySize, EDGE_SMEM);

    zero_kernel<<<1, 1>>>();

    int nTiles = (N + 127) / 128;
    dim3 ngrid(nTiles < 148 ? nTiles : 148, 2);
    node_tc<<<ngrid, 512, NODE_SMEM>>>(node_emb, N,
        w_src1, b_src1, w_src2, b_src2,
        w_dst1, b_dst1, w_dst2, b_dst2);

    int eTiles = (E + 63) / 64;
    int egrid = eTiles < 296 ? eTiles : 296;
    edge_tc<<<egrid, 256, EDGE_SMEM>>>(edge_fea, E,
        w_edge1, b_edge1, w_edge2, b_edge2,
        noise, src, dst, aug);

    if (out_size > E)
        finalize_kernel<<<1, 1>>>(out, 1.f / (float)E);
}